// round 5
// baseline (speedup 1.0000x reference)
#include <cuda_runtime.h>
#include <cuda_bf16.h>
#include <mma.h>
#include <stdint.h>
#include <stddef.h>
#include <math.h>

using namespace nvcuda;

#define NN 200000
#define EE 1600000
#define CC 128
#define NTTS 20000
#define NMOLS 2000

// ---------------- static device scratch (no allocations allowed) ----------------
__device__ float g_t1[(size_t)NN * CC];
__device__ float g_t2[(size_t)NN * CC];
__device__ float g_hs[(size_t)NN * CC];
__device__ float g_hs2[(size_t)NTTS * CC];
__device__ int   g_cnt[NN];
__device__ int   g_rowoff[NN + 1];
__device__ int   g_cursor[NN];
__device__ int   g_bsum[256];
__device__ int   g_col[EE];
__device__ float g_val[EE];
__device__ int   g_ttoff[NTTS + 1];
__device__ int   g_moloff[NMOLS + 1];
__device__ float g_meanbn_tt[(size_t)NTTS * CC];
__device__ float g_gatout_tt[(size_t)NTTS * CC];
__device__ float g_gi_tt[(size_t)NTTS * 3 * CC];
__device__ float g_gh_tt[(size_t)NTTS * 3 * CC];
__device__ float g_ttbn[(size_t)NTTS * CC];
__device__ float g_meanbn_mol[(size_t)NMOLS * CC];
__device__ float g_gatout_mol[(size_t)NMOLS * CC];
__device__ float g_gi_mol[(size_t)NMOLS * 3 * CC];
__device__ float g_gh_mol[(size_t)NMOLS * 3 * CC];
__device__ float g_molout[(size_t)NMOLS * CC];
__device__ float g_ssrc[NN];
__device__ float g_sdst[NTTS];
__device__ float g_vd[CC];
// pre-split weights (bf16 hi/lo), 2048 rows x 128
__device__ __nv_bfloat16 g_whi[2048 * 128];
__device__ __nv_bfloat16 g_wlo[2048 * 128];
// row offsets into g_whi/g_wlo
#define WR_G0 0
#define WR_G1 128
#define WR_S0 256
#define WR_S1 384
#define WR_IH0 512
#define WR_IH1 896
#define WR_HH0 1280
#define WR_HH1 1664

// ---------------- weight split: fp32 -> bf16 hi + bf16 lo ----------------
__global__ void k_wsplit(const float* __restrict__ Wg, const float* __restrict__ Ws,
                         const float* __restrict__ Wih, const float* __restrict__ Whh,
                         __nv_bfloat16* __restrict__ hi, __nv_bfloat16* __restrict__ lo) {
    int idx = blockIdx.x * blockDim.x + threadIdx.x;  // 2048*128
    int row = idx >> 7, c = idx & 127;
    float w;
    if (row < 256)       w = Wg[(size_t)row * 128 + c];
    else if (row < 512)  w = Ws[(size_t)(row - 256) * 128 + c];
    else if (row < 1280) w = Wih[(size_t)(row - 512) * 128 + c];
    else                 w = Whh[(size_t)(row - 1280) * 128 + c];
    __nv_bfloat16 h = __float2bfloat16(w);
    hi[idx] = h;
    lo[idx] = __float2bfloat16(w - __bfloat162float(h));
}

// ---------------- wmma GEMM: Y[M,Nout] = X[M,128] @ W[Nout,128]^T (+bias)
// 3-term bf16 split, fp32 accum. 64x128 tile/block, 256 thr, 2 CTA/SM.
// W comes pre-split (bhi/blo, row-major [*,128]); X split inline.
// Optional fused row-dot with avec -> aout. ----------------
#define LDA 136
#define SM_META 0                 // bias128 f32 | avec128 f32 | parts256 f32 = 2048 B
#define AH_OFF 2048
#define AL_OFF (AH_OFF + 64 * LDA * 2)       // +17408
#define BH_OFF (AL_OFF + 64 * LDA * 2)
#define BL_OFF (BH_OFF + 128 * LDA * 2)      // +34816
#define GEMM_SMEM (BL_OFF + 128 * LDA * 2)   // 2048+17408*2+34816*2 = 106,496
#define C_OFF AH_OFF              // C[64][132] f32 = 33,792 <= 34,816 (Ah+Al)
#define LDC 132

__global__ __launch_bounds__(256) void k_gemm_tc(
    const float* __restrict__ X,
    const __nv_bfloat16* __restrict__ bhi, const __nv_bfloat16* __restrict__ blo,
    const float* __restrict__ bias, float* __restrict__ Y, int M, int Nout,
    const float* __restrict__ avec, float* __restrict__ aout) {
    extern __shared__ char smem[];
    float* biasS = reinterpret_cast<float*>(smem + SM_META);
    float* avecS = biasS + 128;
    float* parts = avecS + 128;
    __nv_bfloat16* Ah = reinterpret_cast<__nv_bfloat16*>(smem + AH_OFF);
    __nv_bfloat16* Al = reinterpret_cast<__nv_bfloat16*>(smem + AL_OFF);
    __nv_bfloat16* Bh = reinterpret_cast<__nv_bfloat16*>(smem + BH_OFF);
    __nv_bfloat16* Bl = reinterpret_cast<__nv_bfloat16*>(smem + BL_OFF);
    float* Cs = reinterpret_cast<float*>(smem + C_OFF);

    int tid = threadIdx.x, wid = tid >> 5;
    int tm = blockIdx.x, tn = blockIdx.y;
    int row0 = tm * 64;

    if (tid < 128) {
        biasS[tid] = bias ? bias[tn * 128 + tid] : 0.f;
        avecS[tid] = avec ? avec[tid] : 0.f;
    }
    // copy pre-split W rows tn*128..+127 into smem (16B vector ops)
    for (int i = tid; i < 128 * 16; i += 256) {
        int r = i >> 4, q = i & 15;
        *reinterpret_cast<uint4*>(&Bh[r * LDA + q * 8]) =
            *reinterpret_cast<const uint4*>(&bhi[(size_t)(tn * 128 + r) * 128 + q * 8]);
        *reinterpret_cast<uint4*>(&Bl[r * LDA + q * 8]) =
            *reinterpret_cast<const uint4*>(&blo[(size_t)(tn * 128 + r) * 128 + q * 8]);
    }
    // convert X rows row0..+63 -> Ah/Al (8B vector stores)
    for (int i = tid; i < 64 * 32; i += 256) {
        int r = i >> 5, kq = i & 31;
        int gr = row0 + r;
        float4 x = make_float4(0.f, 0.f, 0.f, 0.f);
        if (gr < M) x = *reinterpret_cast<const float4*>(&X[(size_t)gr * 128 + kq * 4]);
        __nv_bfloat162 h01 = __floats2bfloat162_rn(x.x, x.y);
        __nv_bfloat162 h23 = __floats2bfloat162_rn(x.z, x.w);
        __nv_bfloat162 l01 = __floats2bfloat162_rn(x.x - __bfloat162float(h01.x),
                                                   x.y - __bfloat162float(h01.y));
        __nv_bfloat162 l23 = __floats2bfloat162_rn(x.z - __bfloat162float(h23.x),
                                                   x.w - __bfloat162float(h23.y));
        *reinterpret_cast<uint2*>(&Ah[r * LDA + kq * 4]) =
            make_uint2(*reinterpret_cast<uint32_t*>(&h01), *reinterpret_cast<uint32_t*>(&h23));
        *reinterpret_cast<uint2*>(&Al[r * LDA + kq * 4]) =
            make_uint2(*reinterpret_cast<uint32_t*>(&l01), *reinterpret_cast<uint32_t*>(&l23));
    }
    __syncthreads();

    // warp tiling: 4(m) x 2(n); each warp 16 rows x 64 cols
    int wm = wid >> 1, wn = wid & 1;
    wmma::fragment<wmma::accumulator, 16, 16, 16, float> c[4];
#pragma unroll
    for (int j = 0; j < 4; j++) wmma::fill_fragment(c[j], 0.f);

    const __nv_bfloat16* Aterm[3] = {Ah, Ah, Al};
    const __nv_bfloat16* Bterm[3] = {Bh, Bl, Bh};
#pragma unroll
    for (int t = 0; t < 3; t++) {
        const __nv_bfloat16* As = Aterm[t];
        const __nv_bfloat16* Bs = Bterm[t];
#pragma unroll
        for (int k0 = 0; k0 < 128; k0 += 16) {
            wmma::fragment<wmma::matrix_a, 16, 16, 16, __nv_bfloat16, wmma::row_major> a;
            wmma::fragment<wmma::matrix_b, 16, 16, 16, __nv_bfloat16, wmma::col_major> b[4];
            wmma::load_matrix_sync(a, &As[(wm * 16) * LDA + k0], LDA);
#pragma unroll
            for (int j = 0; j < 4; j++)
                wmma::load_matrix_sync(b[j], &Bs[(wn * 64 + j * 16) * LDA + k0], LDA);
#pragma unroll
            for (int j = 0; j < 4; j++) wmma::mma_sync(c[j], a, b[j], c[j]);
        }
    }
    __syncthreads();  // done reading A smem; Cs aliases it
#pragma unroll
    for (int j = 0; j < 4; j++)
        wmma::store_matrix_sync(&Cs[(wm * 16) * LDC + wn * 64 + j * 16], c[j], LDC,
                                wmma::mem_row_major);
    __syncthreads();

    // epilogue: thread t -> row t/4, 32-col chunk (t&3)*32
    {
        int r = tid >> 2, ch = (tid & 3) * 32;
        int row = row0 + r;
        float adot = 0.f;
        if (row < M) {
            float* yp = &Y[(size_t)row * Nout + tn * 128 + ch];
#pragma unroll
            for (int j = 0; j < 32; j += 4) {
                float4 v;
                v.x = Cs[r * LDC + ch + j + 0] + biasS[ch + j + 0];
                v.y = Cs[r * LDC + ch + j + 1] + biasS[ch + j + 1];
                v.z = Cs[r * LDC + ch + j + 2] + biasS[ch + j + 2];
                v.w = Cs[r * LDC + ch + j + 3] + biasS[ch + j + 3];
                adot += v.x * avecS[ch + j] + v.y * avecS[ch + j + 1] +
                        v.z * avecS[ch + j + 2] + v.w * avecS[ch + j + 3];
                *reinterpret_cast<float4*>(yp + j) = v;
            }
        }
        if (avec) {
            parts[tid] = adot;
            __syncthreads();
            if ((tid & 3) == 0 && row < M)
                aout[row] = parts[tid] + parts[tid + 1] + parts[tid + 2] + parts[tid + 3];
        }
    }
}

// ---------------- small helpers ----------------
__device__ __forceinline__ float bn_apply(float x, int idx, int ch,
                                          const float* g, const float* b,
                                          const float* m, const float* v) {
    float sc = g[idx * CC + ch] * rsqrtf(v[idx * CC + ch] + 1e-5f);
    return (x - m[idx * CC + ch]) * sc + b[idx * CC + ch];
}
__device__ __forceinline__ float warp_max(float v) {
#pragma unroll
    for (int o = 16; o > 0; o >>= 1) v = fmaxf(v, __shfl_xor_sync(0xffffffffu, v, o));
    return v;
}
__device__ __forceinline__ float warp_sum(float v) {
#pragma unroll
    for (int o = 16; o > 0; o >>= 1) v += __shfl_xor_sync(0xffffffffu, v, o);
    return v;
}

// ---------------- CSR build ----------------
__global__ void k_zero_int(int* p, int n) {
    int i = blockIdx.x * blockDim.x + threadIdx.x;
    if (i < n) p[i] = 0;
}
__global__ void k_hist(const int* __restrict__ idx0, int* __restrict__ cnt) {
    int e = blockIdx.x * blockDim.x + threadIdx.x;
    if (e < EE) atomicAdd(&cnt[idx0[e]], 1);
}
__global__ void k_scan1(const int* __restrict__ in, int* __restrict__ out,
                        int* __restrict__ bsum, int n) {
    __shared__ int sm[1024];
    int i = blockIdx.x * 1024 + threadIdx.x;
    int v = (i < n) ? in[i] : 0;
    sm[threadIdx.x] = v;
    __syncthreads();
    for (int off = 1; off < 1024; off <<= 1) {
        int t = (threadIdx.x >= off) ? sm[threadIdx.x - off] : 0;
        __syncthreads();
        sm[threadIdx.x] += t;
        __syncthreads();
    }
    if (i < n) out[i] = sm[threadIdx.x] - v;  // exclusive
    if (threadIdx.x == 1023) bsum[blockIdx.x] = sm[1023];
}
__global__ void k_scan2(int* __restrict__ bsum, int nb) {
    __shared__ int sm[256];
    int v = (threadIdx.x < nb) ? bsum[threadIdx.x] : 0;
    sm[threadIdx.x] = v;
    __syncthreads();
    for (int off = 1; off < 256; off <<= 1) {
        int t = (threadIdx.x >= off) ? sm[threadIdx.x - off] : 0;
        __syncthreads();
        sm[threadIdx.x] += t;
        __syncthreads();
    }
    if (threadIdx.x < nb) bsum[threadIdx.x] = sm[threadIdx.x] - v;  // exclusive
}
__global__ void k_scan3(int* __restrict__ out, const int* __restrict__ bsum,
                        int n, int total, int* __restrict__ cursor) {
    int i = blockIdx.x * 1024 + threadIdx.x;
    if (i < n) {
        int v = out[i] + bsum[blockIdx.x];
        out[i] = v;
        cursor[i] = v;
    }
    if (i == 0) out[n] = total;
}
__global__ void k_scatter(const int* __restrict__ adj, const float* __restrict__ aval,
                          int* __restrict__ cursor, int* __restrict__ col,
                          float* __restrict__ val) {
    int e = blockIdx.x * blockDim.x + threadIdx.x;
    if (e >= EE) return;
    int r = adj[e];
    int p = atomicAdd(&cursor[r], 1);
    col[p] = adj[EE + e];
    val[p] = aval[e];
}
__global__ void k_segoff(const int* __restrict__ seg, int n, int nseg, int* __restrict__ off) {
    int i = blockIdx.x * blockDim.x + threadIdx.x;
    if (i >= n) return;
    int s = seg[i];
    int p = (i == 0) ? -1 : seg[i - 1];
    for (int t = p + 1; t <= s; ++t) off[t] = i;
    if (i == n - 1)
        for (int t = s + 1; t <= nseg; ++t) off[t] = n;
}

// ---------------- SpMM gather (warp/row, 2-edge unroll) + bias + BN(+relu)(+BN2) ----------------
__global__ void k_spmm(const float* __restrict__ Xin, float* __restrict__ Y,
                       const int* __restrict__ rowoff, const int* __restrict__ col,
                       const float* __restrict__ val, const float* __restrict__ bias,
                       const float* __restrict__ bg, const float* __restrict__ bb,
                       const float* __restrict__ bm, const float* __restrict__ bv,
                       int bnA, int bnB, int M) {
    int gw = (blockIdx.x * blockDim.x + threadIdx.x) >> 5;
    int lane = threadIdx.x & 31;
    if (gw >= M) return;
    int s = rowoff[gw], e = rowoff[gw + 1];
    float acc[4] = {0.f, 0.f, 0.f, 0.f};
    int i = s;
    for (; i + 1 < e; i += 2) {
        int c0 = col[i], c1 = col[i + 1];
        float v0 = val[i], v1 = val[i + 1];
        const float* x0 = Xin + (size_t)c0 * CC;
        const float* x1 = Xin + (size_t)c1 * CC;
#pragma unroll
        for (int j = 0; j < 4; j++)
            acc[j] += v0 * x0[lane + 32 * j] + v1 * x1[lane + 32 * j];
    }
    if (i < e) {
        int c0 = col[i];
        float v0 = val[i];
        const float* x0 = Xin + (size_t)c0 * CC;
#pragma unroll
        for (int j = 0; j < 4; j++) acc[j] += v0 * x0[lane + 32 * j];
    }
    float* yr = Y + (size_t)gw * CC;
#pragma unroll
    for (int j = 0; j < 4; j++) {
        int ch = lane + 32 * j;
        float z = acc[j] + bias[ch];
        z = bn_apply(z, bnA, ch, bg, bb, bm, bv);
        z = fmaxf(z, 0.f);
        if (bnB >= 0) z = bn_apply(z, bnB, ch, bg, bb, bm, bv);
        yr[ch] = z;
    }
}

// ---------------- segment sum pool (warp/segment) + relu + BN ----------------
__global__ void k_segpool(const float* __restrict__ X, float* __restrict__ Y,
                          const int* __restrict__ off, int nseg,
                          const float* bg, const float* bb, const float* bm,
                          const float* bv, int bi) {
    int gw = (blockIdx.x * blockDim.x + threadIdx.x) >> 5;
    int lane = threadIdx.x & 31;
    if (gw >= nseg) return;
    int s = off[gw], e = off[gw + 1];
    float acc[4] = {0.f, 0.f, 0.f, 0.f};
    for (int i = s; i < e; i++) {
        const float* xr = X + (size_t)i * CC;
#pragma unroll
        for (int j = 0; j < 4; j++) acc[j] += xr[lane + 32 * j];
    }
    float* yr = Y + (size_t)gw * CC;
#pragma unroll
    for (int j = 0; j < 4; j++) {
        int ch = lane + 32 * j;
        float z = fmaxf(acc[j], 0.f);
        yr[ch] = bn_apply(z, bi, ch, bg, bb, bm, bv);
    }
}

// vd[c] = sum_o adst[o] * Wdst[o,c]
__global__ void k_vd(const float* __restrict__ Wd, const float* __restrict__ ad,
                     float* __restrict__ vd) {
    int c = threadIdx.x;
    float s = 0.f;
    for (int o = 0; o < CC; o++) s += ad[o] * Wd[o * CC + c];
    vd[c] = s;
}
// out[r] = dot(X[r], v)
__global__ void k_rowdot(const float* __restrict__ X, const float* __restrict__ v,
                         float* __restrict__ out, int M) {
    int gw = (blockIdx.x * blockDim.x + threadIdx.x) >> 5;
    int lane = threadIdx.x & 31;
    if (gw >= M) return;
    const float* xr = X + (size_t)gw * CC;
    float s = 0.f;
#pragma unroll
    for (int j = 0; j < 4; j++) s += xr[lane + 32 * j] * v[lane + 32 * j];
    s = warp_sum(s);
    if (lane == 0) out[gw] = s;
}

// ---------------- GAT segment softmax + weighted aggregate + bias + ELU ----------------
__global__ void k_gat(const float* __restrict__ hs, const float* __restrict__ ssrc,
                      const float* __restrict__ sdst, const int* __restrict__ off,
                      const float* __restrict__ bias, float* __restrict__ out, int nseg) {
    int gw = (blockIdx.x * blockDim.x + threadIdx.x) >> 5;
    int lane = threadIdx.x & 31;
    if (gw >= nseg) return;
    int s = off[gw], e = off[gw + 1];
    float sd = sdst[gw];
    float acc[4] = {0.f, 0.f, 0.f, 0.f};
    if (e > s) {
        float mx = -3.402823e38f;
        for (int i = s + lane; i < e; i += 32) {
            float a = ssrc[i] + sd;
            a = a > 0.f ? a : 0.01f * a;
            mx = fmaxf(mx, a);
        }
        mx = warp_max(mx);
        float den = 0.f;
        for (int i = s + lane; i < e; i += 32) {
            float a = ssrc[i] + sd;
            a = a > 0.f ? a : 0.01f * a;
            den += __expf(a - mx);
        }
        den = warp_sum(den);
        float inv = 1.f / den;
        for (int i = s; i < e; i++) {
            float a = ssrc[i] + sd;
            a = a > 0.f ? a : 0.01f * a;
            float w = __expf(a - mx) * inv;
            const float* hr = hs + (size_t)i * CC;
#pragma unroll
            for (int j = 0; j < 4; j++) acc[j] += w * hr[lane + 32 * j];
        }
    }
    float* yr = out + (size_t)gw * CC;
#pragma unroll
    for (int j = 0; j < 4; j++) {
        int ch = lane + 32 * j;
        float v = acc[j] + bias[ch];
        v = v > 0.f ? v : (__expf(v) - 1.f);  // ELU
        yr[ch] = v;
    }
}

// ---------------- GRU gates + relu + BN(+BN2) ----------------
__global__ void k_gru(const float* __restrict__ gi, const float* __restrict__ gh,
                      const float* __restrict__ h, float* __restrict__ out, int M,
                      const float* bg, const float* bb, const float* bm,
                      const float* bv, int bnA, int bnB) {
    int idx = blockIdx.x * blockDim.x + threadIdx.x;
    if (idx >= M * CC) return;
    int t = idx >> 7, c = idx & 127;
    const float* gir = gi + (size_t)t * 3 * CC;
    const float* ghr = gh + (size_t)t * 3 * CC;
    float r = 1.f / (1.f + __expf(-(gir[c] + ghr[c])));
    float z = 1.f / (1.f + __expf(-(gir[CC + c] + ghr[CC + c])));
    float n = tanhf(gir[2 * CC + c] + r * ghr[2 * CC + c]);
    float hv = (1.f - z) * n + z * h[idx];
    float y = fmaxf(hv, 0.f);
    y = bn_apply(y, bnA, c, bg, bb, bm, bv);
    if (bnB >= 0) y = bn_apply(y, bnB, c, bg, bb, bm, bv);
    out[idx] = y;
}

// ---------------- predictor: relu(mol@W1^T+b1)@W2^T+b2 ----------------
__global__ void k_pred(const float* __restrict__ mol, const float* __restrict__ W1,
                       const float* __restrict__ b1, const float* __restrict__ W2,
                       const float* __restrict__ b2, float* __restrict__ out) {
    __shared__ float xr[CC];
    __shared__ float hr[64];
    int m = blockIdx.x, t = threadIdx.x;
    xr[t] = mol[(size_t)m * CC + t];
    xr[t + 64] = mol[(size_t)m * CC + t + 64];
    __syncthreads();
    float s = b1[t];
    for (int c = 0; c < CC; c++) s += W1[t * CC + c] * xr[c];
    s = fmaxf(s, 0.f);
    hr[t] = s * W2[t];
    __syncthreads();
    for (int off = 32; off > 0; off >>= 1) {
        if (t < off) hr[t] += hr[t + off];
        __syncthreads();
    }
    if (t == 0) out[m] = hr[0] + b2[0];
}

// ---------------- host ----------------
extern "C" void kernel_launch(void* const* d_in, const int* in_sizes, int n_in,
                              void* d_out, int out_size) {
    if (n_in < 24) return;
    const float *node_attr, *adj_value, *W_gcn, *b_gcn, *bg, *bb, *bm, *bv;
    const float *Wsrc, *Wdst, *asrc, *adst, *gbias, *Wih, *Whh, *bih, *bhh;
    const float *pW1, *pb1, *pW2, *pb2;
    const int *adj_index, *ttb, *tgb;
    if (in_sizes[1] == EE) {  // reference-signature order
        node_attr = (const float*)d_in[0];  adj_value = (const float*)d_in[1];
        W_gcn = (const float*)d_in[2];      b_gcn = (const float*)d_in[3];
        bg = (const float*)d_in[4];         bb = (const float*)d_in[5];
        bm = (const float*)d_in[6];         bv = (const float*)d_in[7];
        Wsrc = (const float*)d_in[8];       Wdst = (const float*)d_in[9];
        asrc = (const float*)d_in[10];      adst = (const float*)d_in[11];
        gbias = (const float*)d_in[12];     Wih = (const float*)d_in[13];
        Whh = (const float*)d_in[14];       bih = (const float*)d_in[15];
        bhh = (const float*)d_in[16];       pW1 = (const float*)d_in[17];
        pb1 = (const float*)d_in[18];       pW2 = (const float*)d_in[19];
        pb2 = (const float*)d_in[20];       adj_index = (const int*)d_in[21];
        ttb = (const int*)d_in[22];         tgb = (const int*)d_in[23];
    } else {  // setup_inputs dict order
        node_attr = (const float*)d_in[0];  adj_index = (const int*)d_in[1];
        adj_value = (const float*)d_in[2];  ttb = (const int*)d_in[3];
        tgb = (const int*)d_in[4];          W_gcn = (const float*)d_in[5];
        b_gcn = (const float*)d_in[6];      bg = (const float*)d_in[7];
        bb = (const float*)d_in[8];         bm = (const float*)d_in[9];
        bv = (const float*)d_in[10];        Wsrc = (const float*)d_in[11];
        Wdst = (const float*)d_in[12];      asrc = (const float*)d_in[13];
        adst = (const float*)d_in[14];      gbias = (const float*)d_in[15];
        Wih = (const float*)d_in[16];       Whh = (const float*)d_in[17];
        bih = (const float*)d_in[18];       bhh = (const float*)d_in[19];
        pW1 = (const float*)d_in[20];       pb1 = (const float*)d_in[21];
        pW2 = (const float*)d_in[22];       pb2 = (const float*)d_in[23];
    }

    void* p;
    cudaGetSymbolAddress(&p, g_t1);        float* t1 = (float*)p;
    cudaGetSymbolAddress(&p, g_t2);        float* t2 = (float*)p;
    cudaGetSymbolAddress(&p, g_hs);        float* hs = (float*)p;
    cudaGetSymbolAddress(&p, g_hs2);       float* hs2 = (float*)p;
    cudaGetSymbolAddress(&p, g_cnt);       int* cnt = (int*)p;
    cudaGetSymbolAddress(&p, g_rowoff);    int* rowoff = (int*)p;
    cudaGetSymbolAddress(&p, g_cursor);    int* cursor = (int*)p;
    cudaGetSymbolAddress(&p, g_bsum);      int* bsum = (int*)p;
    cudaGetSymbolAddress(&p, g_col);       int* col = (int*)p;
    cudaGetSymbolAddress(&p, g_val);       float* val = (float*)p;
    cudaGetSymbolAddress(&p, g_ttoff);     int* ttoff = (int*)p;
    cudaGetSymbolAddress(&p, g_moloff);    int* moloff = (int*)p;
    cudaGetSymbolAddress(&p, g_meanbn_tt); float* meanbn_tt = (float*)p;
    cudaGetSymbolAddress(&p, g_gatout_tt); float* gatout_tt = (float*)p;
    cudaGetSymbolAddress(&p, g_gi_tt);     float* gi_tt = (float*)p;
    cudaGetSymbolAddress(&p, g_gh_tt);     float* gh_tt = (float*)p;
    cudaGetSymbolAddress(&p, g_ttbn);      float* ttbn = (float*)p;
    cudaGetSymbolAddress(&p, g_meanbn_mol);float* meanbn_mol = (float*)p;
    cudaGetSymbolAddress(&p, g_gatout_mol);float* gatout_mol = (float*)p;
    cudaGetSymbolAddress(&p, g_gi_mol);    float* gi_mol = (float*)p;
    cudaGetSymbolAddress(&p, g_gh_mol);    float* gh_mol = (float*)p;
    cudaGetSymbolAddress(&p, g_molout);    float* molout = (float*)p;
    cudaGetSymbolAddress(&p, g_ssrc);      float* ssrc = (float*)p;
    cudaGetSymbolAddress(&p, g_sdst);      float* sdst = (float*)p;
    cudaGetSymbolAddress(&p, g_vd);        float* vd = (float*)p;
    cudaGetSymbolAddress(&p, g_whi);       __nv_bfloat16* whi = (__nv_bfloat16*)p;
    cudaGetSymbolAddress(&p, g_wlo);       __nv_bfloat16* wlo = (__nv_bfloat16*)p;
    float* outp = (float*)d_out;

    cudaFuncSetAttribute(k_gemm_tc, cudaFuncAttributeMaxDynamicSharedMemorySize, GEMM_SMEM);

    auto gemm = [&](const float* X, int wrow, const float* bias, float* Y,
                    int M, int Nout, const float* avec, float* aout) {
        dim3 grid((M + 63) / 64, Nout / 128);
        k_gemm_tc<<<grid, 256, GEMM_SMEM>>>(X, whi + (size_t)wrow * 128,
                                            wlo + (size_t)wrow * 128, bias, Y, M, Nout,
                                            avec, aout);
    };

    // ---- weight split + CSR build (big gemm0 placed at launch index 3 for ncu) ----
    k_wsplit<<<1024, 256>>>(W_gcn, Wsrc, Wih, Whh, whi, wlo);          // 0
    k_zero_int<<<(NN + 255) / 256, 256>>>(cnt, NN);                    // 1
    k_hist<<<(EE + 255) / 256, 256>>>(adj_index, cnt);                 // 2
    gemm(node_attr, WR_G0, nullptr, t1, NN, 128, nullptr, nullptr);    // 3 (big GEMM)
    k_scan1<<<196, 1024>>>(cnt, rowoff, bsum, NN);                     // 4
    k_scan2<<<1, 256>>>(bsum, 196);                                    // 5
    k_scan3<<<196, 1024>>>(rowoff, bsum, NN, EE, cursor);              // 6
    k_scatter<<<(EE + 255) / 256, 256>>>(adj_index, adj_value, cursor, col, val);
    k_segoff<<<(NN + 255) / 256, 256>>>(ttb, NN, NTTS, ttoff);
    k_segoff<<<(NTTS + 255) / 256, 256>>>(tgb, NTTS, NMOLS, moloff);

    // ---- GCN layer 0: t2 = relu(bn0(A t1 + b0)) ----
    k_spmm<<<NN / 8, 256>>>(t1, t2, rowoff, col, val, b_gcn, bg, bb, bm, bv, 0, -1, NN);
    // ---- GCN layer 1 (+ fused bn2): t2 = bn2(relu(bn1(A (t2 W1^T) + b1))) ----
    gemm(t2, WR_G1, nullptr, t1, NN, 128, nullptr, nullptr);
    k_spmm<<<NN / 8, 256>>>(t1, t2, rowoff, col, val, b_gcn + CC, bg, bb, bm, bv, 1, 2, NN);

    // ---- tt stage ----
    k_segpool<<<(NTTS * 32 + 255) / 256, 256>>>(t2, meanbn_tt, ttoff, NTTS, bg, bb, bm, bv, 3);
    gemm(t2, WR_S0, nullptr, hs, NN, 128, asrc, ssrc);
    k_vd<<<1, 128>>>(Wdst, adst, vd);
    k_rowdot<<<(NTTS * 32 + 255) / 256, 256>>>(meanbn_tt, vd, sdst, NTTS);
    k_gat<<<(NTTS * 32 + 255) / 256, 256>>>(hs, ssrc, sdst, ttoff, gbias, gatout_tt, NTTS);
    gemm(gatout_tt, WR_IH0, bih, gi_tt, NTTS, 384, nullptr, nullptr);
    gemm(meanbn_tt, WR_HH0, bhh, gh_tt, NTTS, 384, nullptr, nullptr);
    k_gru<<<(NTTS * CC + 255) / 256, 256>>>(gi_tt, gh_tt, meanbn_tt, ttbn, NTTS,
                                            bg, bb, bm, bv, 4, 5);

    // ---- mol stage ----
    k_segpool<<<(NMOLS * 32 + 255) / 256, 256>>>(ttbn, meanbn_mol, moloff, NMOLS, bg, bb, bm, bv, 6);
    gemm(ttbn, WR_S1, nullptr, hs2, NTTS, 128, asrc + CC, ssrc);
    k_vd<<<1, 128>>>(Wdst + CC * CC, adst + CC, vd);
    k_rowdot<<<(NMOLS * 32 + 255) / 256, 256>>>(meanbn_mol, vd, sdst, NMOLS);
    k_gat<<<(NMOLS * 32 + 255) / 256, 256>>>(hs2, ssrc, sdst, moloff, gbias + CC, gatout_mol, NMOLS);
    gemm(gatout_mol, WR_IH1, bih + 3 * CC, gi_mol, NMOLS, 384, nullptr, nullptr);
    gemm(meanbn_mol, WR_HH1, bhh + 3 * CC, gh_mol, NMOLS, 384, nullptr, nullptr);
    k_gru<<<(NMOLS * CC + 255) / 256, 256>>>(gi_mol, gh_mol, meanbn_mol, molout, NMOLS,
                                             bg, bb, bm, bv, 7, -1);

    // ---- predictor ----
    k_pred<<<NMOLS, 64>>>(molout, pW1, pb1, pW2, pb2, outp);
}

// round 6
// speedup vs baseline: 1.1999x; 1.1999x over previous
#include <cuda_runtime.h>
#include <cuda_bf16.h>
#include <mma.h>
#include <stdint.h>
#include <stddef.h>
#include <math.h>

using namespace nvcuda;

#define NN 200000
#define EE 1600000
#define CC 128
#define NTTS 20000
#define NMOLS 2000

// ---------------- static device scratch (no allocations allowed) ----------------
__device__ float g_t1[(size_t)NN * CC];
__device__ float g_t2[(size_t)NN * CC];
__device__ float g_hs[(size_t)NN * CC];
__device__ float g_hs2[(size_t)NTTS * CC];
__device__ int   g_cnt[NN];
__device__ int   g_rowoff[NN + 1];
__device__ int   g_cursor[NN];
__device__ int   g_bsum[256];
__device__ int   g_col[EE];
__device__ float g_val[EE];
__device__ int   g_ttoff[NTTS + 1];
__device__ int   g_moloff[NMOLS + 1];
__device__ float g_meanbn_tt[(size_t)NTTS * CC];
__device__ float g_gi_tt[(size_t)NTTS * 3 * CC];
__device__ float g_gh_tt[(size_t)NTTS * 3 * CC];
__device__ float g_ttbn[(size_t)NTTS * CC];
__device__ float g_meanbn_mol[(size_t)NMOLS * CC];
__device__ float g_gi_mol[(size_t)NMOLS * 3 * CC];
__device__ float g_gh_mol[(size_t)NMOLS * 3 * CC];
__device__ float g_molout[(size_t)NMOLS * CC];
__device__ float g_ssrc[NN];
__device__ float g_sdst[NTTS];
__device__ float g_vd[CC];
// pre-split weights (bf16 hi/lo), 2048 rows x 128
__device__ __nv_bfloat16 g_whi[2048 * 128];
__device__ __nv_bfloat16 g_wlo[2048 * 128];
// bf16 split activation buffers
__device__ __nv_bfloat16 g_xhi[(size_t)NN * CC];
__device__ __nv_bfloat16 g_xlo[(size_t)NN * CC];
__device__ __nv_bfloat16 g_phi[(size_t)NTTS * CC];   // pool-mean splits
__device__ __nv_bfloat16 g_plo[(size_t)NTTS * CC];
__device__ __nv_bfloat16 g_ghi[(size_t)NTTS * CC];   // gat-out / ttbn splits
__device__ __nv_bfloat16 g_glo[(size_t)NTTS * CC];

#define WR_G0 0
#define WR_G1 128
#define WR_S0 256
#define WR_S1 384
#define WR_IH0 512
#define WR_IH1 896
#define WR_HH0 1280
#define WR_HH1 1664

// ---------------- helpers ----------------
__device__ __forceinline__ uint32_t smem_u32(const void* p) {
    uint32_t a;
    asm("{ .reg .u64 t; cvta.to.shared.u64 t, %1; cvt.u32.u64 %0, t; }" : "=r"(a) : "l"(p));
    return a;
}
__device__ __forceinline__ void cp16(uint32_t saddr, const void* g) {
    asm volatile("cp.async.cg.shared.global [%0], [%1], 16;" :: "r"(saddr), "l"(g));
}
#define CP_COMMIT asm volatile("cp.async.commit_group;" ::: "memory")
#define CP_WAIT0 asm volatile("cp.async.wait_group 0;" ::: "memory")

__device__ __forceinline__ void write_split(__nv_bfloat16* hi, __nv_bfloat16* lo,
                                            size_t idx, float z) {
    __nv_bfloat16 h = __float2bfloat16(z);
    hi[idx] = h;
    lo[idx] = __float2bfloat16(z - __bfloat162float(h));
}

// ---------------- weight split: fp32 -> bf16 hi + bf16 lo ----------------
__global__ void k_wsplit(const float* __restrict__ Wg, const float* __restrict__ Ws,
                         const float* __restrict__ Wih, const float* __restrict__ Whh,
                         __nv_bfloat16* __restrict__ hi, __nv_bfloat16* __restrict__ lo) {
    int idx = blockIdx.x * blockDim.x + threadIdx.x;  // 2048*128
    int row = idx >> 7, c = idx & 127;
    float w;
    if (row < 256)       w = Wg[(size_t)row * 128 + c];
    else if (row < 512)  w = Ws[(size_t)(row - 256) * 128 + c];
    else if (row < 1280) w = Wih[(size_t)(row - 512) * 128 + c];
    else                 w = Whh[(size_t)(row - 1280) * 128 + c];
    write_split(hi, lo, idx, w);
}

// ---------------- activation split (node_attr) ----------------
__global__ void k_xsplit(const float* __restrict__ X, __nv_bfloat16* __restrict__ hi,
                         __nv_bfloat16* __restrict__ lo, int n4) {
    int i = blockIdx.x * blockDim.x + threadIdx.x;
    if (i >= n4) return;
    float4 x = reinterpret_cast<const float4*>(X)[i];
    __nv_bfloat162 h01 = __floats2bfloat162_rn(x.x, x.y);
    __nv_bfloat162 h23 = __floats2bfloat162_rn(x.z, x.w);
    __nv_bfloat162 l01 = __floats2bfloat162_rn(x.x - __bfloat162float(h01.x),
                                               x.y - __bfloat162float(h01.y));
    __nv_bfloat162 l23 = __floats2bfloat162_rn(x.z - __bfloat162float(h23.x),
                                               x.w - __bfloat162float(h23.y));
    reinterpret_cast<uint2*>(hi)[i] =
        make_uint2(*reinterpret_cast<uint32_t*>(&h01), *reinterpret_cast<uint32_t*>(&h23));
    reinterpret_cast<uint2*>(lo)[i] =
        make_uint2(*reinterpret_cast<uint32_t*>(&l01), *reinterpret_cast<uint32_t*>(&l23));
}

// ---------------- wmma GEMM v2: Y[M,Nout] = X @ W^T (+bias), X pre-split bf16.
// 3-term split, cp.async loads, persistent grid-stride, 2 CTAs/SM. ----------------
#define LDA 136
#define SM_META 0                 // bias128 | avec128 | parts256 (f32) = 2048 B
#define BH_OFF 2048
#define BL_OFF (BH_OFF + 128 * LDA * 2)     // +34816
#define AB_OFF (BL_OFF + 128 * LDA * 2)     // Ah, then Al at +64*LDA*2
#define GEMM_SMEM (AB_OFF + 128 * LDA * 2)  // 2048 + 3*34816 = 106,496
#define LDC 132                    // Cs aliases AB region: 64*132*4 = 33,792 <= 34,816

__global__ __launch_bounds__(256, 2) void k_gemm_tc(
    const __nv_bfloat16* __restrict__ Xhi, const __nv_bfloat16* __restrict__ Xlo,
    const __nv_bfloat16* __restrict__ bhi, const __nv_bfloat16* __restrict__ blo,
    const float* __restrict__ bias, float* __restrict__ Y, int M, int Nout,
    const float* __restrict__ avec, float* __restrict__ aout) {
    extern __shared__ char smem[];
    float* biasS = reinterpret_cast<float*>(smem + SM_META);
    float* avecS = biasS + 128;
    float* parts = avecS + 128;
    __nv_bfloat16* Bh = reinterpret_cast<__nv_bfloat16*>(smem + BH_OFF);
    __nv_bfloat16* Bl = reinterpret_cast<__nv_bfloat16*>(smem + BL_OFF);
    __nv_bfloat16* Ah = reinterpret_cast<__nv_bfloat16*>(smem + AB_OFF);
    __nv_bfloat16* Al = Ah + 64 * LDA;
    float* Cs = reinterpret_cast<float*>(smem + AB_OFF);

    int tid = threadIdx.x, wid = tid >> 5;
    int tn = blockIdx.y;
    int ntiles = (M + 63) >> 6;
    if ((int)blockIdx.x >= ntiles) return;
    uint32_t sb = smem_u32(smem);

    // B tile via cp.async (persistent: loaded once)
    for (int i = tid; i < 128 * 16; i += 256) {
        int r = i >> 4, c = i & 15;
        cp16(sb + BH_OFF + r * (LDA * 2) + c * 16, &bhi[(size_t)(tn * 128 + r) * 128 + c * 8]);
        cp16(sb + BL_OFF + r * (LDA * 2) + c * 16, &blo[(size_t)(tn * 128 + r) * 128 + c * 8]);
    }
    CP_COMMIT;
    if (tid < 128) {
        biasS[tid] = bias ? bias[tn * 128 + tid] : 0.f;
        avecS[tid] = avec ? avec[tid] : 0.f;
    }
    int wm = wid >> 1, wn = wid & 1;

    for (int tm = blockIdx.x; tm < ntiles; tm += gridDim.x) {
        int row0 = tm * 64;
        // A tile (hi+lo) via cp.async, rows clamped to stay in-bounds
        for (int i = tid; i < 64 * 16; i += 256) {
            int r = i >> 4, c = i & 15;
            int gr = row0 + r;
            if (gr >= M) gr = M - 1;
            cp16(sb + AB_OFF + r * (LDA * 2) + c * 16, &Xhi[(size_t)gr * 128 + c * 8]);
            cp16(sb + AB_OFF + 64 * (LDA * 2) + r * (LDA * 2) + c * 16,
                 &Xlo[(size_t)gr * 128 + c * 8]);
        }
        CP_COMMIT;
        CP_WAIT0;
        __syncthreads();

        wmma::fragment<wmma::accumulator, 16, 16, 16, float> c4[4];
#pragma unroll
        for (int j = 0; j < 4; j++) wmma::fill_fragment(c4[j], 0.f);
        const __nv_bfloat16* Aterm[3] = {Ah, Ah, Al};
        const __nv_bfloat16* Bterm[3] = {Bh, Bl, Bh};
#pragma unroll
        for (int t = 0; t < 3; t++) {
            const __nv_bfloat16* As = Aterm[t];
            const __nv_bfloat16* Bs = Bterm[t];
#pragma unroll
            for (int k0 = 0; k0 < 128; k0 += 16) {
                wmma::fragment<wmma::matrix_a, 16, 16, 16, __nv_bfloat16, wmma::row_major> a;
                wmma::fragment<wmma::matrix_b, 16, 16, 16, __nv_bfloat16, wmma::col_major> b[4];
                wmma::load_matrix_sync(a, &As[(wm * 16) * LDA + k0], LDA);
#pragma unroll
                for (int j = 0; j < 4; j++)
                    wmma::load_matrix_sync(b[j], &Bs[(wn * 64 + j * 16) * LDA + k0], LDA);
#pragma unroll
                for (int j = 0; j < 4; j++) wmma::mma_sync(c4[j], a, b[j], c4[j]);
            }
        }
        __syncthreads();  // all warps done reading A smem; Cs aliases it
#pragma unroll
        for (int j = 0; j < 4; j++)
            wmma::store_matrix_sync(&Cs[(wm * 16) * LDC + wn * 64 + j * 16], c4[j], LDC,
                                    wmma::mem_row_major);
        __syncthreads();

        // epilogue: thread t -> row t/4, 32-col chunk (t&3)*32
        int r = tid >> 2, ch = (tid & 3) * 32;
        int row = row0 + r;
        float adot = 0.f;
        if (row < M) {
            float* yp = &Y[(size_t)row * Nout + tn * 128 + ch];
#pragma unroll
            for (int j = 0; j < 32; j += 4) {
                float4 v;
                v.x = Cs[r * LDC + ch + j + 0] + biasS[ch + j + 0];
                v.y = Cs[r * LDC + ch + j + 1] + biasS[ch + j + 1];
                v.z = Cs[r * LDC + ch + j + 2] + biasS[ch + j + 2];
                v.w = Cs[r * LDC + ch + j + 3] + biasS[ch + j + 3];
                adot += v.x * avecS[ch + j] + v.y * avecS[ch + j + 1] +
                        v.z * avecS[ch + j + 2] + v.w * avecS[ch + j + 3];
                *reinterpret_cast<float4*>(yp + j) = v;
            }
        }
        if (avec) {
            parts[tid] = adot;
            __syncthreads();
            if ((tid & 3) == 0 && row < M)
                aout[row] = parts[tid] + parts[tid + 1] + parts[tid + 2] + parts[tid + 3];
        }
        __syncthreads();  // Cs / A buffer free for next iteration's cp.async
    }
}

// ---------------- small helpers ----------------
__device__ __forceinline__ float bn_apply(float x, int idx, int ch,
                                          const float* g, const float* b,
                                          const float* m, const float* v) {
    float sc = g[idx * CC + ch] * rsqrtf(v[idx * CC + ch] + 1e-5f);
    return (x - m[idx * CC + ch]) * sc + b[idx * CC + ch];
}
__device__ __forceinline__ float warp_max(float v) {
#pragma unroll
    for (int o = 16; o > 0; o >>= 1) v = fmaxf(v, __shfl_xor_sync(0xffffffffu, v, o));
    return v;
}
__device__ __forceinline__ float warp_sum(float v) {
#pragma unroll
    for (int o = 16; o > 0; o >>= 1) v += __shfl_xor_sync(0xffffffffu, v, o);
    return v;
}

// ---------------- CSR build ----------------
__global__ void k_zero_int(int* p, int n) {
    int i = blockIdx.x * blockDim.x + threadIdx.x;
    if (i < n) p[i] = 0;
}
__global__ void k_hist(const int* __restrict__ idx0, int* __restrict__ cnt) {
    int e = blockIdx.x * blockDim.x + threadIdx.x;
    if (e < EE) atomicAdd(&cnt[idx0[e]], 1);
}
__global__ void k_scan1(const int* __restrict__ in, int* __restrict__ out,
                        int* __restrict__ bsum, int n) {
    __shared__ int sm[1024];
    int i = blockIdx.x * 1024 + threadIdx.x;
    int v = (i < n) ? in[i] : 0;
    sm[threadIdx.x] = v;
    __syncthreads();
    for (int off = 1; off < 1024; off <<= 1) {
        int t = (threadIdx.x >= off) ? sm[threadIdx.x - off] : 0;
        __syncthreads();
        sm[threadIdx.x] += t;
        __syncthreads();
    }
    if (i < n) out[i] = sm[threadIdx.x] - v;  // exclusive
    if (threadIdx.x == 1023) bsum[blockIdx.x] = sm[1023];
}
__global__ void k_scan2(int* __restrict__ bsum, int nb) {
    __shared__ int sm[256];
    int v = (threadIdx.x < nb) ? bsum[threadIdx.x] : 0;
    sm[threadIdx.x] = v;
    __syncthreads();
    for (int off = 1; off < 256; off <<= 1) {
        int t = (threadIdx.x >= off) ? sm[threadIdx.x - off] : 0;
        __syncthreads();
        sm[threadIdx.x] += t;
        __syncthreads();
    }
    if (threadIdx.x < nb) bsum[threadIdx.x] = sm[threadIdx.x] - v;  // exclusive
}
__global__ void k_scan3(int* __restrict__ out, const int* __restrict__ bsum,
                        int n, int total, int* __restrict__ cursor) {
    int i = blockIdx.x * 1024 + threadIdx.x;
    if (i < n) {
        int v = out[i] + bsum[blockIdx.x];
        out[i] = v;
        cursor[i] = v;
    }
    if (i == 0) out[n] = total;
}
__global__ void k_scatter(const int* __restrict__ adj, const float* __restrict__ aval,
                          int* __restrict__ cursor, int* __restrict__ col,
                          float* __restrict__ val) {
    int e = blockIdx.x * blockDim.x + threadIdx.x;
    if (e >= EE) return;
    int r = adj[e];
    int p = atomicAdd(&cursor[r], 1);
    col[p] = adj[EE + e];
    val[p] = aval[e];
}
__global__ void k_segoff(const int* __restrict__ seg, int n, int nseg, int* __restrict__ off) {
    int i = blockIdx.x * blockDim.x + threadIdx.x;
    if (i >= n) return;
    int s = seg[i];
    int p = (i == 0) ? -1 : seg[i - 1];
    for (int t = p + 1; t <= s; ++t) off[t] = i;
    if (i == n - 1)
        for (int t = s + 1; t <= nseg; ++t) off[t] = n;
}

// ---------------- SpMM gather + bias + BN(+relu)(+BN2); f32 and/or bf16-split out ----------------
__global__ void k_spmm(const float* __restrict__ Xin, float* __restrict__ Yf,
                       __nv_bfloat16* __restrict__ Yhi, __nv_bfloat16* __restrict__ Ylo,
                       const int* __restrict__ rowoff, const int* __restrict__ col,
                       const float* __restrict__ val, const float* __restrict__ bias,
                       const float* __restrict__ bg, const float* __restrict__ bb,
                       const float* __restrict__ bm, const float* __restrict__ bv,
                       int bnA, int bnB, int M) {
    int gw = (blockIdx.x * blockDim.x + threadIdx.x) >> 5;
    int lane = threadIdx.x & 31;
    if (gw >= M) return;
    int s = rowoff[gw], e = rowoff[gw + 1];
    float acc[4] = {0.f, 0.f, 0.f, 0.f};
    int i = s;
    for (; i + 1 < e; i += 2) {
        int c0 = col[i], c1 = col[i + 1];
        float v0 = val[i], v1 = val[i + 1];
        const float* x0 = Xin + (size_t)c0 * CC;
        const float* x1 = Xin + (size_t)c1 * CC;
#pragma unroll
        for (int j = 0; j < 4; j++)
            acc[j] += v0 * x0[lane + 32 * j] + v1 * x1[lane + 32 * j];
    }
    if (i < e) {
        int c0 = col[i];
        float v0 = val[i];
        const float* x0 = Xin + (size_t)c0 * CC;
#pragma unroll
        for (int j = 0; j < 4; j++) acc[j] += v0 * x0[lane + 32 * j];
    }
#pragma unroll
    for (int j = 0; j < 4; j++) {
        int ch = lane + 32 * j;
        float z = acc[j] + bias[ch];
        z = bn_apply(z, bnA, ch, bg, bb, bm, bv);
        z = fmaxf(z, 0.f);
        if (bnB >= 0) z = bn_apply(z, bnB, ch, bg, bb, bm, bv);
        size_t idx = (size_t)gw * CC + ch;
        if (Yf) Yf[idx] = z;
        if (Yhi) write_split(Yhi, Ylo, idx, z);
    }
}

// ---------------- segment sum pool + relu + BN; f32 + bf16-split out ----------------
__global__ void k_segpool(const float* __restrict__ X, float* __restrict__ Yf,
                          __nv_bfloat16* __restrict__ Yhi, __nv_bfloat16* __restrict__ Ylo,
                          const int* __restrict__ off, int nseg,
                          const float* bg, const float* bb, const float* bm,
                          const float* bv, int bi) {
    int gw = (blockIdx.x * blockDim.x + threadIdx.x) >> 5;
    int lane = threadIdx.x & 31;
    if (gw >= nseg) return;
    int s = off[gw], e = off[gw + 1];
    float acc[4] = {0.f, 0.f, 0.f, 0.f};
    for (int i = s; i < e; i++) {
        const float* xr = X + (size_t)i * CC;
#pragma unroll
        for (int j = 0; j < 4; j++) acc[j] += xr[lane + 32 * j];
    }
#pragma unroll
    for (int j = 0; j < 4; j++) {
        int ch = lane + 32 * j;
        float z = bn_apply(fmaxf(acc[j], 0.f), bi, ch, bg, bb, bm, bv);
        size_t idx = (size_t)gw * CC + ch;
        Yf[idx] = z;
        write_split(Yhi, Ylo, idx, z);
    }
}

// vd[c] = sum_o adst[o] * Wdst[o,c]
__global__ void k_vd(const float* __restrict__ Wd, const float* __restrict__ ad,
                     float* __restrict__ vd) {
    int c = threadIdx.x;
    float s = 0.f;
    for (int o = 0; o < CC; o++) s += ad[o] * Wd[o * CC + c];
    vd[c] = s;
}
__global__ void k_rowdot(const float* __restrict__ X, const float* __restrict__ v,
                         float* __restrict__ out, int M) {
    int gw = (blockIdx.x * blockDim.x + threadIdx.x) >> 5;
    int lane = threadIdx.x & 31;
    if (gw >= M) return;
    const float* xr = X + (size_t)gw * CC;
    float s = 0.f;
#pragma unroll
    for (int j = 0; j < 4; j++) s += xr[lane + 32 * j] * v[lane + 32 * j];
    s = warp_sum(s);
    if (lane == 0) out[gw] = s;
}

// ---------------- GAT softmax + aggregate + bias + ELU -> bf16-split out ----------------
__global__ void k_gat(const float* __restrict__ hs, const float* __restrict__ ssrc,
                      const float* __restrict__ sdst, const int* __restrict__ off,
                      const float* __restrict__ bias, __nv_bfloat16* __restrict__ outhi,
                      __nv_bfloat16* __restrict__ outlo, int nseg) {
    int gw = (blockIdx.x * blockDim.x + threadIdx.x) >> 5;
    int lane = threadIdx.x & 31;
    if (gw >= nseg) return;
    int s = off[gw], e = off[gw + 1];
    float sd = sdst[gw];
    float acc[4] = {0.f, 0.f, 0.f, 0.f};
    if (e > s) {
        float mx = -3.402823e38f;
        for (int i = s + lane; i < e; i += 32) {
            float a = ssrc[i] + sd;
            a = a > 0.f ? a : 0.01f * a;
            mx = fmaxf(mx, a);
        }
        mx = warp_max(mx);
        float den = 0.f;
        for (int i = s + lane; i < e; i += 32) {
            float a = ssrc[i] + sd;
            a = a > 0.f ? a : 0.01f * a;
            den += __expf(a - mx);
        }
        den = warp_sum(den);
        float inv = 1.f / den;
        for (int i = s; i < e; i++) {
            float a = ssrc[i] + sd;
            a = a > 0.f ? a : 0.01f * a;
            float w = __expf(a - mx) * inv;
            const float* hr = hs + (size_t)i * CC;
#pragma unroll
            for (int j = 0; j < 4; j++) acc[j] += w * hr[lane + 32 * j];
        }
    }
#pragma unroll
    for (int j = 0; j < 4; j++) {
        int ch = lane + 32 * j;
        float v = acc[j] + bias[ch];
        v = v > 0.f ? v : (__expf(v) - 1.f);  // ELU
        write_split(outhi, outlo, (size_t)gw * CC + ch, v);
    }
}

// ---------------- GRU gates + relu + BN(+BN2); f32 (+ optional bf16-split) out ----------------
__global__ void k_gru(const float* __restrict__ gi, const float* __restrict__ gh,
                      const float* __restrict__ h, float* __restrict__ outf,
                      __nv_bfloat16* __restrict__ outhi, __nv_bfloat16* __restrict__ outlo,
                      int M, const float* bg, const float* bb, const float* bm,
                      const float* bv, int bnA, int bnB) {
    int idx = blockIdx.x * blockDim.x + threadIdx.x;
    if (idx >= M * CC) return;
    int t = idx >> 7, c = idx & 127;
    const float* gir = gi + (size_t)t * 3 * CC;
    const float* ghr = gh + (size_t)t * 3 * CC;
    float r = 1.f / (1.f + __expf(-(gir[c] + ghr[c])));
    float z = 1.f / (1.f + __expf(-(gir[CC + c] + ghr[CC + c])));
    float n = tanhf(gir[2 * CC + c] + r * ghr[2 * CC + c]);
    float hv = (1.f - z) * n + z * h[idx];
    float y = fmaxf(hv, 0.f);
    y = bn_apply(y, bnA, c, bg, bb, bm, bv);
    if (bnB >= 0) y = bn_apply(y, bnB, c, bg, bb, bm, bv);
    outf[idx] = y;
    if (outhi) write_split(outhi, outlo, idx, y);
}

// ---------------- predictor ----------------
__global__ void k_pred(const float* __restrict__ mol, const float* __restrict__ W1,
                       const float* __restrict__ b1, const float* __restrict__ W2,
                       const float* __restrict__ b2, float* __restrict__ out) {
    __shared__ float xr[CC];
    __shared__ float hr[64];
    int m = blockIdx.x, t = threadIdx.x;
    xr[t] = mol[(size_t)m * CC + t];
    xr[t + 64] = mol[(size_t)m * CC + t + 64];
    __syncthreads();
    float s = b1[t];
    for (int c = 0; c < CC; c++) s += W1[t * CC + c] * xr[c];
    s = fmaxf(s, 0.f);
    hr[t] = s * W2[t];
    __syncthreads();
    for (int off = 32; off > 0; off >>= 1) {
        if (t < off) hr[t] += hr[t + off];
        __syncthreads();
    }
    if (t == 0) out[m] = hr[0] + b2[0];
}

// ---------------- host ----------------
extern "C" void kernel_launch(void* const* d_in, const int* in_sizes, int n_in,
                              void* d_out, int out_size) {
    if (n_in < 24) return;
    const float *node_attr, *adj_value, *W_gcn, *b_gcn, *bg, *bb, *bm, *bv;
    const float *Wsrc, *Wdst, *asrc, *adst, *gbias, *Wih, *Whh, *bih, *bhh;
    const float *pW1, *pb1, *pW2, *pb2;
    const int *adj_index, *ttb, *tgb;
    if (in_sizes[1] == EE) {  // reference-signature order
        node_attr = (const float*)d_in[0];  adj_value = (const float*)d_in[1];
        W_gcn = (const float*)d_in[2];      b_gcn = (const float*)d_in[3];
        bg = (const float*)d_in[4];         bb = (const float*)d_in[5];
        bm = (const float*)d_in[6];         bv = (const float*)d_in[7];
        Wsrc = (const float*)d_in[8];       Wdst = (const float*)d_in[9];
        asrc = (const float*)d_in[10];      adst = (const float*)d_in[11];
        gbias = (const float*)d_in[12];     Wih = (const float*)d_in[13];
        Whh = (const float*)d_in[14];       bih = (const float*)d_in[15];
        bhh = (const float*)d_in[16];       pW1 = (const float*)d_in[17];
        pb1 = (const float*)d_in[18];       pW2 = (const float*)d_in[19];
        pb2 = (const float*)d_in[20];       adj_index = (const int*)d_in[21];
        ttb = (const int*)d_in[22];         tgb = (const int*)d_in[23];
    } else {  // setup_inputs dict order
        node_attr = (const float*)d_in[0];  adj_index = (const int*)d_in[1];
        adj_value = (const float*)d_in[2];  ttb = (const int*)d_in[3];
        tgb = (const int*)d_in[4];          W_gcn = (const float*)d_in[5];
        b_gcn = (const float*)d_in[6];      bg = (const float*)d_in[7];
        bb = (const float*)d_in[8];         bm = (const float*)d_in[9];
        bv = (const float*)d_in[10];        Wsrc = (const float*)d_in[11];
        Wdst = (const float*)d_in[12];      asrc = (const float*)d_in[13];
        adst = (const float*)d_in[14];      gbias = (const float*)d_in[15];
        Wih = (const float*)d_in[16];       Whh = (const float*)d_in[17];
        bih = (const float*)d_in[18];       bhh = (const float*)d_in[19];
        pW1 = (const float*)d_in[20];       pb1 = (const float*)d_in[21];
        pW2 = (const float*)d_in[22];       pb2 = (const float*)d_in[23];
    }

    void* p;
    cudaGetSymbolAddress(&p, g_t1);        float* t1 = (float*)p;
    cudaGetSymbolAddress(&p, g_t2);        float* t2 = (float*)p;
    cudaGetSymbolAddress(&p, g_hs);        float* hs = (float*)p;
    cudaGetSymbolAddress(&p, g_hs2);       float* hs2 = (float*)p;
    cudaGetSymbolAddress(&p, g_cnt);       int* cnt = (int*)p;
    cudaGetSymbolAddress(&p, g_rowoff);    int* rowoff = (int*)p;
    cudaGetSymbolAddress(&p, g_cursor);    int* cursor = (int*)p;
    cudaGetSymbolAddress(&p, g_bsum);      int* bsum = (int*)p;
    cudaGetSymbolAddress(&p, g_col);       int* col = (int*)p;
    cudaGetSymbolAddress(&p, g_val);       float* val = (float*)p;
    cudaGetSymbolAddress(&p, g_ttoff);     int* ttoff = (int*)p;
    cudaGetSymbolAddress(&p, g_moloff);    int* moloff = (int*)p;
    cudaGetSymbolAddress(&p, g_meanbn_tt); float* meanbn_tt = (float*)p;
    cudaGetSymbolAddress(&p, g_gi_tt);     float* gi_tt = (float*)p;
    cudaGetSymbolAddress(&p, g_gh_tt);     float* gh_tt = (float*)p;
    cudaGetSymbolAddress(&p, g_ttbn);      float* ttbn = (float*)p;
    cudaGetSymbolAddress(&p, g_meanbn_mol);float* meanbn_mol = (float*)p;
    cudaGetSymbolAddress(&p, g_gi_mol);    float* gi_mol = (float*)p;
    cudaGetSymbolAddress(&p, g_gh_mol);    float* gh_mol = (float*)p;
    cudaGetSymbolAddress(&p, g_molout);    float* molout = (float*)p;
    cudaGetSymbolAddress(&p, g_ssrc);      float* ssrc = (float*)p;
    cudaGetSymbolAddress(&p, g_sdst);      float* sdst = (float*)p;
    cudaGetSymbolAddress(&p, g_vd);        float* vd = (float*)p;
    cudaGetSymbolAddress(&p, g_whi);       __nv_bfloat16* whi = (__nv_bfloat16*)p;
    cudaGetSymbolAddress(&p, g_wlo);       __nv_bfloat16* wlo = (__nv_bfloat16*)p;
    cudaGetSymbolAddress(&p, g_xhi);       __nv_bfloat16* xhi = (__nv_bfloat16*)p;
    cudaGetSymbolAddress(&p, g_xlo);       __nv_bfloat16* xlo = (__nv_bfloat16*)p;
    cudaGetSymbolAddress(&p, g_phi);       __nv_bfloat16* phi = (__nv_bfloat16*)p;
    cudaGetSymbolAddress(&p, g_plo);       __nv_bfloat16* plo = (__nv_bfloat16*)p;
    cudaGetSymbolAddress(&p, g_ghi);       __nv_bfloat16* ghi = (__nv_bfloat16*)p;
    cudaGetSymbolAddress(&p, g_glo);       __nv_bfloat16* glo = (__nv_bfloat16*)p;
    float* outp = (float*)d_out;

    cudaFuncSetAttribute(k_gemm_tc, cudaFuncAttributeMaxDynamicSharedMemorySize, GEMM_SMEM);

    auto gemm = [&](const __nv_bfloat16* xh, const __nv_bfloat16* xl, int wrow,
                    const float* bias, float* Y, int M, int Nout,
                    const float* avec, float* aout) {
        int ntiles = (M + 63) / 64;
        int gx = ntiles < 592 ? ntiles : 592;
        dim3 grid(gx, Nout / 128);
        k_gemm_tc<<<grid, 256, GEMM_SMEM>>>(xh, xl, whi + (size_t)wrow * 128,
                                            wlo + (size_t)wrow * 128, bias, Y, M, Nout,
                                            avec, aout);
    };

    // launch order: gemm1 at index 3 (ncu capture slot)
    k_wsplit<<<1024, 256>>>(W_gcn, Wsrc, Wih, Whh, whi, wlo);            // 0
    k_xsplit<<<(NN * 32 + 255) / 256, 256>>>(node_attr, xhi, xlo, NN * 32);  // 1
    k_zero_int<<<(NN + 255) / 256, 256>>>(cnt, NN);                      // 2
    gemm(xhi, xlo, WR_G0, nullptr, t1, NN, 128, nullptr, nullptr);       // 3 big GEMM
    k_hist<<<(EE + 255) / 256, 256>>>(adj_index, cnt);
    k_scan1<<<196, 1024>>>(cnt, rowoff, bsum, NN);
    k_scan2<<<1, 256>>>(bsum, 196);
    k_scan3<<<196, 1024>>>(rowoff, bsum, NN, EE, cursor);
    k_scatter<<<(EE + 255) / 256, 256>>>(adj_index, adj_value, cursor, col, val);
    k_segoff<<<(NN + 255) / 256, 256>>>(ttb, NN, NTTS, ttoff);
    k_segoff<<<(NTTS + 255) / 256, 256>>>(tgb, NTTS, NMOLS, moloff);

    // GCN layer 0: xsplit(relu(bn0(A t1 + b0))) -> xhi/xlo (gemm-only consumer)
    k_spmm<<<NN / 8, 256>>>(t1, nullptr, xhi, xlo, rowoff, col, val, b_gcn,
                            bg, bb, bm, bv, 0, -1, NN);
    // GCN layer 1 (+ fused bn2): t2 f32 + split
    gemm(xhi, xlo, WR_G1, nullptr, t1, NN, 128, nullptr, nullptr);
    k_spmm<<<NN / 8, 256>>>(t1, t2, xhi, xlo, rowoff, col, val, b_gcn + CC,
                            bg, bb, bm, bv, 1, 2, NN);

    // tt stage
    k_segpool<<<(NTTS * 32 + 255) / 256, 256>>>(t2, meanbn_tt, phi, plo, ttoff, NTTS,
                                                bg, bb, bm, bv, 3);
    gemm(xhi, xlo, WR_S0, nullptr, hs, NN, 128, asrc, ssrc);
    k_vd<<<1, 128>>>(Wdst, adst, vd);
    k_rowdot<<<(NTTS * 32 + 255) / 256, 256>>>(meanbn_tt, vd, sdst, NTTS);
    k_gat<<<(NTTS * 32 + 255) / 256, 256>>>(hs, ssrc, sdst, ttoff, gbias, ghi, glo, NTTS);
    gemm(ghi, glo, WR_IH0, bih, gi_tt, NTTS, 384, nullptr, nullptr);
    gemm(phi, plo, WR_HH0, bhh, gh_tt, NTTS, 384, nullptr, nullptr);
    k_gru<<<(NTTS * CC + 255) / 256, 256>>>(gi_tt, gh_tt, meanbn_tt, ttbn, ghi, glo,
                                            NTTS, bg, bb, bm, bv, 4, 5);

    // mol stage
    k_segpool<<<(NMOLS * 32 + 255) / 256, 256>>>(ttbn, meanbn_mol, phi, plo, moloff, NMOLS,
                                                 bg, bb, bm, bv, 6);
    gemm(ghi, glo, WR_S1, nullptr, hs2, NTTS, 128, asrc + CC, ssrc);
    k_vd<<<1, 128>>>(Wdst + CC * CC, adst + CC, vd);
    k_rowdot<<<(NMOLS * 32 + 255) / 256, 256>>>(meanbn_mol, vd, sdst, NMOLS);
    k_gat<<<(NMOLS * 32 + 255) / 256, 256>>>(hs2, ssrc, sdst, moloff, gbias + CC,
                                             ghi, glo, NMOLS);
    gemm(ghi, glo, WR_IH1, bih + 3 * CC, gi_mol, NMOLS, 384, nullptr, nullptr);
    gemm(phi, plo, WR_HH1, bhh + 3 * CC, gh_mol, NMOLS, 384, nullptr, nullptr);
    k_gru<<<(NMOLS * CC + 255) / 256, 256>>>(gi_mol, gh_mol, meanbn_mol, molout,
                                             nullptr, nullptr, NMOLS,
                                             bg, bb, bm, bv, 7, -1);

    // predictor
    k_pred<<<NMOLS, 64>>>(molout, pW1, pb1, pW2, pb2, outp);
}

// round 7
// speedup vs baseline: 1.3688x; 1.1407x over previous
#include <cuda_runtime.h>
#include <cuda_bf16.h>
#include <mma.h>
#include <stdint.h>
#include <stddef.h>
#include <math.h>

using namespace nvcuda;

#define NN 200000
#define EE 1600000
#define CC 128
#define NTTS 20000
#define NMOLS 2000

// ---------------- static device scratch ----------------
__device__ float g_t1[(size_t)NN * CC];
__device__ float g_t2[(size_t)NN * CC];
__device__ float g_hs[(size_t)NN * CC];
__device__ float g_hs2[(size_t)NTTS * CC];
__device__ int   g_cnt[NN];
__device__ int   g_rowoff[NN + 1];
__device__ int   g_cursor[NN];
__device__ int   g_bsum[256];
__device__ int   g_col[EE];
__device__ float g_val[EE];
__device__ int   g_ttoff[NTTS + 1];
__device__ int   g_moloff[NMOLS + 1];
__device__ float g_meanbn_tt[(size_t)NTTS * CC];
__device__ float g_gi_tt[(size_t)NTTS * 3 * CC];
__device__ float g_gh_tt[(size_t)NTTS * 3 * CC];
__device__ float g_ttbn[(size_t)NTTS * CC];
__device__ float g_meanbn_mol[(size_t)NMOLS * CC];
__device__ float g_gi_mol[(size_t)NMOLS * 3 * CC];
__device__ float g_gh_mol[(size_t)NMOLS * 3 * CC];
__device__ float g_molout[(size_t)NMOLS * CC];
__device__ float g_ssrc[NN];
__device__ float g_sdst[NTTS];
__device__ float g_vsrc[CC];
__device__ float g_vdst[CC];
__device__ __nv_bfloat16 g_whi[2048 * 128];
__device__ __nv_bfloat16 g_wlo[2048 * 128];
__device__ __nv_bfloat16 g_xhi[(size_t)NN * CC];
__device__ __nv_bfloat16 g_xlo[(size_t)NN * CC];
__device__ __nv_bfloat16 g_phi[(size_t)NTTS * CC];
__device__ __nv_bfloat16 g_plo[(size_t)NTTS * CC];
__device__ __nv_bfloat16 g_ghi[(size_t)NTTS * CC];
__device__ __nv_bfloat16 g_glo[(size_t)NTTS * CC];

#define WR_G0 0
#define WR_G1 128
#define WR_S0 256
#define WR_S1 384
#define WR_IH0 512
#define WR_IH1 896
#define WR_HH0 1280
#define WR_HH1 1664

// ---------------- helpers ----------------
__device__ __forceinline__ uint32_t smem_u32(const void* p) {
    uint32_t a;
    asm("{ .reg .u64 t; cvta.to.shared.u64 t, %1; cvt.u32.u64 %0, t; }" : "=r"(a) : "l"(p));
    return a;
}
__device__ __forceinline__ void cp16(uint32_t saddr, const void* g) {
    asm volatile("cp.async.cg.shared.global [%0], [%1], 16;" :: "r"(saddr), "l"(g));
}
#define CP_COMMIT asm volatile("cp.async.commit_group;" ::: "memory")
#define CP_WAIT0 asm volatile("cp.async.wait_group 0;" ::: "memory")

__device__ __forceinline__ void write_split(__nv_bfloat16* hi, __nv_bfloat16* lo,
                                            size_t idx, float z) {
    __nv_bfloat16 h = __float2bfloat16(z);
    hi[idx] = h;
    lo[idx] = __float2bfloat16(z - __bfloat162float(h));
}

// ---------------- weight split ----------------
__global__ void k_wsplit(const float* __restrict__ Wg, const float* __restrict__ Ws,
                         const float* __restrict__ Wih, const float* __restrict__ Whh,
                         __nv_bfloat16* __restrict__ hi, __nv_bfloat16* __restrict__ lo) {
    int idx = blockIdx.x * blockDim.x + threadIdx.x;
    int row = idx >> 7, c = idx & 127;
    float w;
    if (row < 256)       w = Wg[(size_t)row * 128 + c];
    else if (row < 512)  w = Ws[(size_t)(row - 256) * 128 + c];
    else if (row < 1280) w = Wih[(size_t)(row - 512) * 128 + c];
    else                 w = Whh[(size_t)(row - 1280) * 128 + c];
    write_split(hi, lo, idx, w);
}

// ---------------- activation split (node_attr) ----------------
__global__ void k_xsplit(const float* __restrict__ X, __nv_bfloat16* __restrict__ hi,
                         __nv_bfloat16* __restrict__ lo, int n4) {
    int i = blockIdx.x * blockDim.x + threadIdx.x;
    if (i >= n4) return;
    float4 x = reinterpret_cast<const float4*>(X)[i];
    __nv_bfloat162 h01 = __floats2bfloat162_rn(x.x, x.y);
    __nv_bfloat162 h23 = __floats2bfloat162_rn(x.z, x.w);
    __nv_bfloat162 l01 = __floats2bfloat162_rn(x.x - __bfloat162float(h01.x),
                                               x.y - __bfloat162float(h01.y));
    __nv_bfloat162 l23 = __floats2bfloat162_rn(x.z - __bfloat162float(h23.x),
                                               x.w - __bfloat162float(h23.y));
    reinterpret_cast<uint2*>(hi)[i] =
        make_uint2(*reinterpret_cast<uint32_t*>(&h01), *reinterpret_cast<uint32_t*>(&h23));
    reinterpret_cast<uint2*>(lo)[i] =
        make_uint2(*reinterpret_cast<uint32_t*>(&l01), *reinterpret_cast<uint32_t*>(&l23));
}

// ---------------- wmma GEMM v3: Y = X @ W^T, pure (no bias/epilogue),
// 3-term bf16 split, direct fragment store to gmem, persistent, 2 CTA/SM ----------------
#define LDA 136
#define BH_OFF 0
#define BL_OFF (BH_OFF + 128 * LDA * 2)
#define AH_OFF (BL_OFF + 128 * LDA * 2)
#define AL_OFF (AH_OFF + 64 * LDA * 2)
#define GEMM_SMEM (AH_OFF + 2 * 64 * LDA * 2)   // 104,448 B

__global__ __launch_bounds__(256, 2) void k_gemm_tc(
    const __nv_bfloat16* __restrict__ Xhi, const __nv_bfloat16* __restrict__ Xlo,
    const __nv_bfloat16* __restrict__ bhi, const __nv_bfloat16* __restrict__ blo,
    float* __restrict__ Y, int M, int Nout) {
    extern __shared__ char smem[];
    __nv_bfloat16* Bh = reinterpret_cast<__nv_bfloat16*>(smem + BH_OFF);
    __nv_bfloat16* Bl = reinterpret_cast<__nv_bfloat16*>(smem + BL_OFF);
    __nv_bfloat16* Ah = reinterpret_cast<__nv_bfloat16*>(smem + AH_OFF);
    __nv_bfloat16* Al = reinterpret_cast<__nv_bfloat16*>(smem + AL_OFF);

    int tid = threadIdx.x, wid = tid >> 5;
    int tn = blockIdx.y;
    int ntiles = (M + 63) >> 6;
    if ((int)blockIdx.x >= ntiles) return;
    uint32_t sb = smem_u32(smem);

    // B tile (loaded once per block)
    for (int i = tid; i < 128 * 16; i += 256) {
        int r = i >> 4, c = i & 15;
        cp16(sb + BH_OFF + r * (LDA * 2) + c * 16, &bhi[(size_t)(tn * 128 + r) * 128 + c * 8]);
        cp16(sb + BL_OFF + r * (LDA * 2) + c * 16, &blo[(size_t)(tn * 128 + r) * 128 + c * 8]);
    }
    CP_COMMIT;

    int wm = wid & 1, wn = wid >> 1;   // wm: 0..1 (32 rows), wn: 0..3 (32 cols)

    for (int tm = blockIdx.x; tm < ntiles; tm += gridDim.x) {
        int row0 = tm * 64;
        for (int i = tid; i < 64 * 16; i += 256) {
            int r = i >> 4, c = i & 15;
            int gr = row0 + r;
            if (gr >= M) gr = M - 1;
            cp16(sb + AH_OFF + r * (LDA * 2) + c * 16, &Xhi[(size_t)gr * 128 + c * 8]);
            cp16(sb + AL_OFF + r * (LDA * 2) + c * 16, &Xlo[(size_t)gr * 128 + c * 8]);
        }
        CP_COMMIT;
        CP_WAIT0;
        __syncthreads();

        wmma::fragment<wmma::accumulator, 16, 16, 16, float> c4[2][2];
#pragma unroll
        for (int i = 0; i < 2; i++)
#pragma unroll
            for (int j = 0; j < 2; j++) wmma::fill_fragment(c4[i][j], 0.f);

        const __nv_bfloat16* Aterm[3] = {Ah, Ah, Al};
        const __nv_bfloat16* Bterm[3] = {Bh, Bl, Bh};
#pragma unroll
        for (int t = 0; t < 3; t++) {
            const __nv_bfloat16* As = Aterm[t];
            const __nv_bfloat16* Bs = Bterm[t];
#pragma unroll
            for (int k0 = 0; k0 < 128; k0 += 16) {
                wmma::fragment<wmma::matrix_a, 16, 16, 16, __nv_bfloat16, wmma::row_major> a[2];
                wmma::fragment<wmma::matrix_b, 16, 16, 16, __nv_bfloat16, wmma::col_major> b[2];
#pragma unroll
                for (int i = 0; i < 2; i++)
                    wmma::load_matrix_sync(a[i], &As[(wm * 32 + i * 16) * LDA + k0], LDA);
#pragma unroll
                for (int j = 0; j < 2; j++)
                    wmma::load_matrix_sync(b[j], &Bs[(wn * 32 + j * 16) * LDA + k0], LDA);
#pragma unroll
                for (int i = 0; i < 2; i++)
#pragma unroll
                    for (int j = 0; j < 2; j++) wmma::mma_sync(c4[i][j], a[i], b[j], c4[i][j]);
            }
        }
        // direct store to gmem (M is always a multiple of 16 -> no partial fragments)
#pragma unroll
        for (int i = 0; i < 2; i++) {
            int row = row0 + wm * 32 + i * 16;
            if (row + 16 <= M) {
#pragma unroll
                for (int j = 0; j < 2; j++)
                    wmma::store_matrix_sync(&Y[(size_t)row * Nout + tn * 128 + wn * 32 + j * 16],
                                            c4[i][j], Nout, wmma::mem_row_major);
            }
        }
        __syncthreads();  // A buffer free for next iteration
    }
}

// ---------------- small helpers ----------------
__device__ __forceinline__ float bn_apply(float x, int idx, int ch,
                                          const float* g, const float* b,
                                          const float* m, const float* v) {
    float sc = g[idx * CC + ch] * rsqrtf(v[idx * CC + ch] + 1e-5f);
    return (x - m[idx * CC + ch]) * sc + b[idx * CC + ch];
}
__device__ __forceinline__ float warp_max(float v) {
#pragma unroll
    for (int o = 16; o > 0; o >>= 1) v = fmaxf(v, __shfl_xor_sync(0xffffffffu, v, o));
    return v;
}
__device__ __forceinline__ float warp_sum(float v) {
#pragma unroll
    for (int o = 16; o > 0; o >>= 1) v += __shfl_xor_sync(0xffffffffu, v, o);
    return v;
}

// ---------------- CSR build ----------------
__global__ void k_zero_int(int* p, int n) {
    int i = blockIdx.x * blockDim.x + threadIdx.x;
    if (i < n) p[i] = 0;
}
__global__ void k_hist(const int* __restrict__ idx0, int* __restrict__ cnt) {
    int e = blockIdx.x * blockDim.x + threadIdx.x;
    if (e < EE) atomicAdd(&cnt[idx0[e]], 1);
}
__global__ void k_scan1(const int* __restrict__ in, int* __restrict__ out,
                        int* __restrict__ bsum, int n) {
    __shared__ int sm[1024];
    int i = blockIdx.x * 1024 + threadIdx.x;
    int v = (i < n) ? in[i] : 0;
    sm[threadIdx.x] = v;
    __syncthreads();
    for (int off = 1; off < 1024; off <<= 1) {
        int t = (threadIdx.x >= off) ? sm[threadIdx.x - off] : 0;
        __syncthreads();
        sm[threadIdx.x] += t;
        __syncthreads();
    }
    if (i < n) out[i] = sm[threadIdx.x] - v;
    if (threadIdx.x == 1023) bsum[blockIdx.x] = sm[1023];
}
__global__ void k_scan2(int* __restrict__ bsum, int nb) {
    __shared__ int sm[256];
    int v = (threadIdx.x < nb) ? bsum[threadIdx.x] : 0;
    sm[threadIdx.x] = v;
    __syncthreads();
    for (int off = 1; off < 256; off <<= 1) {
        int t = (threadIdx.x >= off) ? sm[threadIdx.x - off] : 0;
        __syncthreads();
        sm[threadIdx.x] += t;
        __syncthreads();
    }
    if (threadIdx.x < nb) bsum[threadIdx.x] = sm[threadIdx.x] - v;
}
__global__ void k_scan3(int* __restrict__ out, const int* __restrict__ bsum,
                        int n, int total, int* __restrict__ cursor) {
    int i = blockIdx.x * 1024 + threadIdx.x;
    if (i < n) {
        int v = out[i] + bsum[blockIdx.x];
        out[i] = v;
        cursor[i] = v;
    }
    if (i == 0) out[n] = total;
}
__global__ void k_scatter(const int* __restrict__ adj, const float* __restrict__ aval,
                          int* __restrict__ cursor, int* __restrict__ col,
                          float* __restrict__ val) {
    int e = blockIdx.x * blockDim.x + threadIdx.x;
    if (e >= EE) return;
    int r = adj[e];
    int p = atomicAdd(&cursor[r], 1);
    col[p] = adj[EE + e];
    val[p] = aval[e];
}
__global__ void k_segoff(const int* __restrict__ seg, int n, int nseg, int* __restrict__ off) {
    int i = blockIdx.x * blockDim.x + threadIdx.x;
    if (i >= n) return;
    int s = seg[i];
    int p = (i == 0) ? -1 : seg[i - 1];
    for (int t = p + 1; t <= s; ++t) off[t] = i;
    if (i == n - 1)
        for (int t = s + 1; t <= nseg; ++t) off[t] = n;
}

// ---------------- SpMM + bias + BN(+relu)(+BN2), f32/bf16-split out, fused rowdot ----------------
__global__ void k_spmm(const float* __restrict__ Xin, float* __restrict__ Yf,
                       __nv_bfloat16* __restrict__ Yhi, __nv_bfloat16* __restrict__ Ylo,
                       const int* __restrict__ rowoff, const int* __restrict__ col,
                       const float* __restrict__ val, const float* __restrict__ bias,
                       const float* __restrict__ vsrc, float* __restrict__ svout,
                       const float* __restrict__ bg, const float* __restrict__ bb,
                       const float* __restrict__ bm, const float* __restrict__ bv,
                       int bnA, int bnB, int M) {
    int gw = (blockIdx.x * blockDim.x + threadIdx.x) >> 5;
    int lane = threadIdx.x & 31;
    if (gw >= M) return;
    int s = rowoff[gw], e = rowoff[gw + 1];
    float acc[4] = {0.f, 0.f, 0.f, 0.f};
    int i = s;
    for (; i + 1 < e; i += 2) {
        int c0 = col[i], c1 = col[i + 1];
        float v0 = val[i], v1 = val[i + 1];
        const float* x0 = Xin + (size_t)c0 * CC;
        const float* x1 = Xin + (size_t)c1 * CC;
#pragma unroll
        for (int j = 0; j < 4; j++)
            acc[j] += v0 * x0[lane + 32 * j] + v1 * x1[lane + 32 * j];
    }
    if (i < e) {
        int c0 = col[i];
        float v0 = val[i];
        const float* x0 = Xin + (size_t)c0 * CC;
#pragma unroll
        for (int j = 0; j < 4; j++) acc[j] += v0 * x0[lane + 32 * j];
    }
    float sdot = 0.f;
#pragma unroll
    for (int j = 0; j < 4; j++) {
        int ch = lane + 32 * j;
        float z = acc[j] + bias[ch];
        z = bn_apply(z, bnA, ch, bg, bb, bm, bv);
        z = fmaxf(z, 0.f);
        if (bnB >= 0) z = bn_apply(z, bnB, ch, bg, bb, bm, bv);
        size_t idx = (size_t)gw * CC + ch;
        if (Yf) Yf[idx] = z;
        if (Yhi) write_split(Yhi, Ylo, idx, z);
        if (vsrc) sdot += z * vsrc[ch];
    }
    if (vsrc) {
        sdot = warp_sum(sdot);
        if (lane == 0) svout[gw] = sdot;
    }
}

// ---------------- segment sum pool + relu + BN; f32 + bf16-split out ----------------
__global__ void k_segpool(const float* __restrict__ X, float* __restrict__ Yf,
                          __nv_bfloat16* __restrict__ Yhi, __nv_bfloat16* __restrict__ Ylo,
                          const int* __restrict__ off, int nseg,
                          const float* bg, const float* bb, const float* bm,
                          const float* bv, int bi) {
    int gw = (blockIdx.x * blockDim.x + threadIdx.x) >> 5;
    int lane = threadIdx.x & 31;
    if (gw >= nseg) return;
    int s = off[gw], e = off[gw + 1];
    float acc[4] = {0.f, 0.f, 0.f, 0.f};
    for (int i = s; i < e; i++) {
        const float* xr = X + (size_t)i * CC;
#pragma unroll
        for (int j = 0; j < 4; j++) acc[j] += xr[lane + 32 * j];
    }
#pragma unroll
    for (int j = 0; j < 4; j++) {
        int ch = lane + 32 * j;
        float z = bn_apply(fmaxf(acc[j], 0.f), bi, ch, bg, bb, bm, bv);
        size_t idx = (size_t)gw * CC + ch;
        Yf[idx] = z;
        write_split(Yhi, Ylo, idx, z);
    }
}

// vd[c] = sum_o ad[o] * Wd[o,c]
__global__ void k_vd(const float* __restrict__ Wd, const float* __restrict__ ad,
                     float* __restrict__ vd) {
    int c = threadIdx.x;
    float s = 0.f;
    for (int o = 0; o < CC; o++) s += ad[o] * Wd[o * CC + c];
    vd[c] = s;
}
__global__ void k_rowdot(const float* __restrict__ X, const float* __restrict__ v,
                         float* __restrict__ out, int M) {
    int gw = (blockIdx.x * blockDim.x + threadIdx.x) >> 5;
    int lane = threadIdx.x & 31;
    if (gw >= M) return;
    const float* xr = X + (size_t)gw * CC;
    float s = 0.f;
#pragma unroll
    for (int j = 0; j < 4; j++) s += xr[lane + 32 * j] * v[lane + 32 * j];
    s = warp_sum(s);
    if (lane == 0) out[gw] = s;
}

// ---------------- GAT softmax + aggregate + bias + ELU -> bf16-split out ----------------
__global__ void k_gat(const float* __restrict__ hs, const float* __restrict__ ssrc,
                      const float* __restrict__ sdst, const int* __restrict__ off,
                      const float* __restrict__ bias, __nv_bfloat16* __restrict__ outhi,
                      __nv_bfloat16* __restrict__ outlo, int nseg) {
    int gw = (blockIdx.x * blockDim.x + threadIdx.x) >> 5;
    int lane = threadIdx.x & 31;
    if (gw >= nseg) return;
    int s = off[gw], e = off[gw + 1];
    float sd = sdst[gw];
    float acc[4] = {0.f, 0.f, 0.f, 0.f};
    if (e > s) {
        float mx = -3.402823e38f;
        for (int i = s + lane; i < e; i += 32) {
            float a = ssrc[i] + sd;
            a = a > 0.f ? a : 0.01f * a;
            mx = fmaxf(mx, a);
        }
        mx = warp_max(mx);
        float den = 0.f;
        for (int i = s + lane; i < e; i += 32) {
            float a = ssrc[i] + sd;
            a = a > 0.f ? a : 0.01f * a;
            den += __expf(a - mx);
        }
        den = warp_sum(den);
        float inv = 1.f / den;
        for (int i = s; i < e; i++) {
            float a = ssrc[i] + sd;
            a = a > 0.f ? a : 0.01f * a;
            float w = __expf(a - mx) * inv;
            const float* hr = hs + (size_t)i * CC;
#pragma unroll
            for (int j = 0; j < 4; j++) acc[j] += w * hr[lane + 32 * j];
        }
    }
#pragma unroll
    for (int j = 0; j < 4; j++) {
        int ch = lane + 32 * j;
        float v = acc[j] + bias[ch];
        v = v > 0.f ? v : (__expf(v) - 1.f);  // ELU
        write_split(outhi, outlo, (size_t)gw * CC + ch, v);
    }
}

// ---------------- GRU gates (+ folded biases) + relu + BN(+BN2) ----------------
__global__ void k_gru(const float* __restrict__ gi, const float* __restrict__ gh,
                      const float* __restrict__ h, const float* __restrict__ bih,
                      const float* __restrict__ bhh, float* __restrict__ outf,
                      __nv_bfloat16* __restrict__ outhi, __nv_bfloat16* __restrict__ outlo,
                      int M, const float* bg, const float* bb, const float* bm,
                      const float* bv, int bnA, int bnB) {
    int idx = blockIdx.x * blockDim.x + threadIdx.x;
    if (idx >= M * CC) return;
    int t = idx >> 7, c = idx & 127;
    const float* gir = gi + (size_t)t * 3 * CC;
    const float* ghr = gh + (size_t)t * 3 * CC;
    float r = 1.f / (1.f + __expf(-(gir[c] + bih[c] + ghr[c] + bhh[c])));
    float z = 1.f / (1.f + __expf(-(gir[CC + c] + bih[CC + c] + ghr[CC + c] + bhh[CC + c])));
    float n = tanhf(gir[2 * CC + c] + bih[2 * CC + c] +
                    r * (ghr[2 * CC + c] + bhh[2 * CC + c]));
    float hv = (1.f - z) * n + z * h[idx];
    float y = fmaxf(hv, 0.f);
    y = bn_apply(y, bnA, c, bg, bb, bm, bv);
    if (bnB >= 0) y = bn_apply(y, bnB, c, bg, bb, bm, bv);
    outf[idx] = y;
    if (outhi) write_split(outhi, outlo, idx, y);
}

// ---------------- predictor ----------------
__global__ void k_pred(const float* __restrict__ mol, const float* __restrict__ W1,
                       const float* __restrict__ b1, const float* __restrict__ W2,
                       const float* __restrict__ b2, float* __restrict__ out) {
    __shared__ float xr[CC];
    __shared__ float hr[64];
    int m = blockIdx.x, t = threadIdx.x;
    xr[t] = mol[(size_t)m * CC + t];
    xr[t + 64] = mol[(size_t)m * CC + t + 64];
    __syncthreads();
    float s = b1[t];
    for (int c = 0; c < CC; c++) s += W1[t * CC + c] * xr[c];
    s = fmaxf(s, 0.f);
    hr[t] = s * W2[t];
    __syncthreads();
    for (int off = 32; off > 0; off >>= 1) {
        if (t < off) hr[t] += hr[t + off];
        __syncthreads();
    }
    if (t == 0) out[m] = hr[0] + b2[0];
}

// ---------------- host ----------------
extern "C" void kernel_launch(void* const* d_in, const int* in_sizes, int n_in,
                              void* d_out, int out_size) {
    if (n_in < 24) return;
    const float *node_attr, *adj_value, *W_gcn, *b_gcn, *bg, *bb, *bm, *bv;
    const float *Wsrc, *Wdst, *asrc, *adst, *gbias, *Wih, *Whh, *bih, *bhh;
    const float *pW1, *pb1, *pW2, *pb2;
    const int *adj_index, *ttb, *tgb;
    if (in_sizes[1] == EE) {
        node_attr = (const float*)d_in[0];  adj_value = (const float*)d_in[1];
        W_gcn = (const float*)d_in[2];      b_gcn = (const float*)d_in[3];
        bg = (const float*)d_in[4];         bb = (const float*)d_in[5];
        bm = (const float*)d_in[6];         bv = (const float*)d_in[7];
        Wsrc = (const float*)d_in[8];       Wdst = (const float*)d_in[9];
        asrc = (const float*)d_in[10];      adst = (const float*)d_in[11];
        gbias = (const float*)d_in[12];     Wih = (const float*)d_in[13];
        Whh = (const float*)d_in[14];       bih = (const float*)d_in[15];
        bhh = (const float*)d_in[16];       pW1 = (const float*)d_in[17];
        pb1 = (const float*)d_in[18];       pW2 = (const float*)d_in[19];
        pb2 = (const float*)d_in[20];       adj_index = (const int*)d_in[21];
        ttb = (const int*)d_in[22];         tgb = (const int*)d_in[23];
    } else {
        node_attr = (const float*)d_in[0];  adj_index = (const int*)d_in[1];
        adj_value = (const float*)d_in[2];  ttb = (const int*)d_in[3];
        tgb = (const int*)d_in[4];          W_gcn = (const float*)d_in[5];
        b_gcn = (const float*)d_in[6];      bg = (const float*)d_in[7];
        bb = (const float*)d_in[8];         bm = (const float*)d_in[9];
        bv = (const float*)d_in[10];        Wsrc = (const float*)d_in[11];
        Wdst = (const float*)d_in[12];      asrc = (const float*)d_in[13];
        adst = (const float*)d_in[14];      gbias = (const float*)d_in[15];
        Wih = (const float*)d_in[16];       Whh = (const float*)d_in[17];
        bih = (const float*)d_in[18];       bhh = (const float*)d_in[19];
        pW1 = (const float*)d_in[20];       pb1 = (const float*)d_in[21];
        pW2 = (const float*)d_in[22];       pb2 = (const float*)d_in[23];
    }

    void* p;
    cudaGetSymbolAddress(&p, g_t1);        float* t1 = (float*)p;
    cudaGetSymbolAddress(&p, g_t2);        float* t2 = (float*)p;
    cudaGetSymbolAddress(&p, g_hs);        float* hs = (float*)p;
    cudaGetSymbolAddress(&p, g_hs2);       float* hs2 = (float*)p;
    cudaGetSymbolAddress(&p, g_cnt);       int* cnt = (int*)p;
    cudaGetSymbolAddress(&p, g_rowoff);    int* rowoff = (int*)p;
    cudaGetSymbolAddress(&p, g_cursor);    int* cursor = (int*)p;
    cudaGetSymbolAddress(&p, g_bsum);      int* bsum = (int*)p;
    cudaGetSymbolAddress(&p, g_col);       int* col = (int*)p;
    cudaGetSymbolAddress(&p, g_val);       float* val = (float*)p;
    cudaGetSymbolAddress(&p, g_ttoff);     int* ttoff = (int*)p;
    cudaGetSymbolAddress(&p, g_moloff);    int* moloff = (int*)p;
    cudaGetSymbolAddress(&p, g_meanbn_tt); float* meanbn_tt = (float*)p;
    cudaGetSymbolAddress(&p, g_gi_tt);     float* gi_tt = (float*)p;
    cudaGetSymbolAddress(&p, g_gh_tt);     float* gh_tt = (float*)p;
    cudaGetSymbolAddress(&p, g_ttbn);      float* ttbn = (float*)p;
    cudaGetSymbolAddress(&p, g_meanbn_mol);float* meanbn_mol = (float*)p;
    cudaGetSymbolAddress(&p, g_gi_mol);    float* gi_mol = (float*)p;
    cudaGetSymbolAddress(&p, g_gh_mol);    float* gh_mol = (float*)p;
    cudaGetSymbolAddress(&p, g_molout);    float* molout = (float*)p;
    cudaGetSymbolAddress(&p, g_ssrc);      float* ssrc = (float*)p;
    cudaGetSymbolAddress(&p, g_sdst);      float* sdst = (float*)p;
    cudaGetSymbolAddress(&p, g_vsrc);      float* vsrc = (float*)p;
    cudaGetSymbolAddress(&p, g_vdst);      float* vdst = (float*)p;
    cudaGetSymbolAddress(&p, g_whi);       __nv_bfloat16* whi = (__nv_bfloat16*)p;
    cudaGetSymbolAddress(&p, g_wlo);       __nv_bfloat16* wlo = (__nv_bfloat16*)p;
    cudaGetSymbolAddress(&p, g_xhi);       __nv_bfloat16* xhi = (__nv_bfloat16*)p;
    cudaGetSymbolAddress(&p, g_xlo);       __nv_bfloat16* xlo = (__nv_bfloat16*)p;
    cudaGetSymbolAddress(&p, g_phi);       __nv_bfloat16* phi = (__nv_bfloat16*)p;
    cudaGetSymbolAddress(&p, g_plo);       __nv_bfloat16* plo = (__nv_bfloat16*)p;
    cudaGetSymbolAddress(&p, g_ghi);       __nv_bfloat16* ghi = (__nv_bfloat16*)p;
    cudaGetSymbolAddress(&p, g_glo);       __nv_bfloat16* glo = (__nv_bfloat16*)p;
    float* outp = (float*)d_out;

    cudaFuncSetAttribute(k_gemm_tc, cudaFuncAttributeMaxDynamicSharedMemorySize, GEMM_SMEM);

    auto gemm = [&](const __nv_bfloat16* xh, const __nv_bfloat16* xl, int wrow,
                    float* Y, int M, int Nout) {
        int ntiles = (M + 63) / 64;
        int gx = ntiles < 592 ? ntiles : 592;
        dim3 grid(gx, Nout / 128);
        k_gemm_tc<<<grid, 256, GEMM_SMEM>>>(xh, xl, whi + (size_t)wrow * 128,
                                            wlo + (size_t)wrow * 128, Y, M, Nout);
    };

    // index 3 = first big GEMM (ncu capture slot)
    k_wsplit<<<1024, 256>>>(W_gcn, Wsrc, Wih, Whh, whi, wlo);                // 0
    k_xsplit<<<(NN * 32 + 255) / 256, 256>>>(node_attr, xhi, xlo, NN * 32);  // 1
    k_zero_int<<<(NN + 255) / 256, 256>>>(cnt, NN);                          // 2
    gemm(xhi, xlo, WR_G0, t1, NN, 128);                                      // 3
    k_hist<<<(EE + 255) / 256, 256>>>(adj_index, cnt);
    k_scan1<<<196, 1024>>>(cnt, rowoff, bsum, NN);
    k_scan2<<<1, 256>>>(bsum, 196);
    k_scan3<<<196, 1024>>>(rowoff, bsum, NN, EE, cursor);
    k_scatter<<<(EE + 255) / 256, 256>>>(adj_index, adj_value, cursor, col, val);
    k_segoff<<<(NN + 255) / 256, 256>>>(ttb, NN, NTTS, ttoff);
    k_segoff<<<(NTTS + 255) / 256, 256>>>(tgb, NTTS, NMOLS, moloff);
    k_vd<<<1, 128>>>(Wsrc, asrc, vsrc);   // vsrc = Wsrc^T asrc  (tt ssrc vector)
    k_vd<<<1, 128>>>(Wdst, adst, vdst);   // vdst = Wdst^T adst  (tt sdst vector)

    // GCN layer 0 -> xhi/xlo only
    k_spmm<<<NN / 8, 256>>>(t1, nullptr, xhi, xlo, rowoff, col, val, b_gcn,
                            nullptr, nullptr, bg, bb, bm, bv, 0, -1, NN);
    // GCN layer 1 (+ fused bn2) -> t2 f32 + split + fused ssrc rowdot
    gemm(xhi, xlo, WR_G1, t1, NN, 128);
    k_spmm<<<NN / 8, 256>>>(t1, t2, xhi, xlo, rowoff, col, val, b_gcn + CC,
                            vsrc, ssrc, bg, bb, bm, bv, 1, 2, NN);

    // tt stage
    k_segpool<<<(NTTS * 32 + 255) / 256, 256>>>(t2, meanbn_tt, phi, plo, ttoff, NTTS,
                                                bg, bb, bm, bv, 3);
    gemm(xhi, xlo, WR_S0, hs, NN, 128);
    k_rowdot<<<(NTTS * 32 + 255) / 256, 256>>>(meanbn_tt, vdst, sdst, NTTS);
    k_gat<<<(NTTS * 32 + 255) / 256, 256>>>(hs, ssrc, sdst, ttoff, gbias, ghi, glo, NTTS);
    gemm(ghi, glo, WR_IH0, gi_tt, NTTS, 384);
    gemm(phi, plo, WR_HH0, gh_tt, NTTS, 384);
    k_gru<<<(NTTS * CC + 255) / 256, 256>>>(gi_tt, gh_tt, meanbn_tt, bih, bhh,
                                            ttbn, ghi, glo, NTTS, bg, bb, bm, bv, 4, 5);

    // mol stage
    k_segpool<<<(NMOLS * 32 + 255) / 256, 256>>>(ttbn, meanbn_mol, phi, plo, moloff, NMOLS,
                                                 bg, bb, bm, bv, 6);
    gemm(ghi, glo, WR_S1, hs2, NTTS, 128);
    k_vd<<<1, 128>>>(Wsrc + CC * CC, asrc + CC, vsrc);
    k_vd<<<1, 128>>>(Wdst + CC * CC, adst + CC, vdst);
    k_rowdot<<<(NTTS * 32 + 255) / 256, 256>>>(ttbn, vsrc, ssrc, NTTS);
    k_rowdot<<<(NMOLS * 32 + 255) / 256, 256>>>(meanbn_mol, vdst, sdst, NMOLS);
    k_gat<<<(NMOLS * 32 + 255) / 256, 256>>>(hs2, ssrc, sdst, moloff, gbias + CC,
                                             ghi, glo, NMOLS);
    gemm(ghi, glo, WR_IH1, gi_mol, NMOLS, 384);
    gemm(phi, plo, WR_HH1, gh_mol, NMOLS, 384);
    k_gru<<<(NMOLS * CC + 255) / 256, 256>>>(gi_mol, gh_mol, meanbn_mol, bih + 3 * CC,
                                             bhh + 3 * CC, molout, nullptr, nullptr,
                                             NMOLS, bg, bb, bm, bv, 7, -1);

    // predictor
    k_pred<<<NMOLS, 64>>>(molout, pW1, pb1, pW2, pb2, outp);
}

// round 8
// speedup vs baseline: 1.5918x; 1.1629x over previous
#include <cuda_runtime.h>
#include <cuda_bf16.h>
#include <mma.h>
#include <stdint.h>
#include <stddef.h>
#include <math.h>

using namespace nvcuda;

#define NN 200000
#define EE 1600000
#define CC 128
#define NTTS 20000
#define NMOLS 2000

// ---------------- static device scratch ----------------
__device__ float g_t1[(size_t)NN * CC];
__device__ float g_t2[(size_t)NN * CC];
__device__ float g_hs[(size_t)NN * CC];
__device__ float g_hs2[(size_t)NTTS * CC];
__device__ int   g_cnt[NN];
__device__ int   g_rowoff[NN + 1];
__device__ int   g_cursor[NN];
__device__ int   g_bsum[256];
__device__ int   g_col[EE];
__device__ float g_val[EE];
__device__ int   g_ttoff[NTTS + 1];
__device__ int   g_moloff[NMOLS + 1];
__device__ float g_meanbn_tt[(size_t)NTTS * CC];
__device__ float g_gi_tt[(size_t)NTTS * 3 * CC];
__device__ float g_gh_tt[(size_t)NTTS * 3 * CC];
__device__ float g_ttbn[(size_t)NTTS * CC];
__device__ float g_meanbn_mol[(size_t)NMOLS * CC];
__device__ float g_gi_mol[(size_t)NMOLS * 3 * CC];
__device__ float g_gh_mol[(size_t)NMOLS * 3 * CC];
__device__ float g_molout[(size_t)NMOLS * CC];
__device__ float g_ssrc[NN];
__device__ float g_sdst[NTTS];
__device__ float g_vsrc[CC];
__device__ float g_vdst[CC];
__device__ __nv_bfloat16 g_whi[2048 * 128];
__device__ __nv_bfloat16 g_wlo[2048 * 128];
__device__ __nv_bfloat16 g_xhi[(size_t)NN * CC];
__device__ __nv_bfloat16 g_xlo[(size_t)NN * CC];
__device__ __nv_bfloat16 g_phi[(size_t)NTTS * CC];
__device__ __nv_bfloat16 g_plo[(size_t)NTTS * CC];
__device__ __nv_bfloat16 g_ghi[(size_t)NTTS * CC];
__device__ __nv_bfloat16 g_glo[(size_t)NTTS * CC];

#define WR_G0 0
#define WR_G1 128
#define WR_S0 256
#define WR_S1 384
#define WR_IH0 512
#define WR_IH1 896
#define WR_HH0 1280
#define WR_HH1 1664

// ---------------- helpers ----------------
__device__ __forceinline__ uint32_t smem_u32(const void* p) {
    uint32_t a;
    asm("{ .reg .u64 t; cvta.to.shared.u64 t, %1; cvt.u32.u64 %0, t; }" : "=r"(a) : "l"(p));
    return a;
}
__device__ __forceinline__ void cp16(uint32_t saddr, const void* g) {
    asm volatile("cp.async.cg.shared.global [%0], [%1], 16;" :: "r"(saddr), "l"(g));
}
#define CP_COMMIT asm volatile("cp.async.commit_group;" ::: "memory")
#define CP_WAIT(n) asm volatile("cp.async.wait_group %0;" :: "n"(n) : "memory")

__device__ __forceinline__ void write_split(__nv_bfloat16* hi, __nv_bfloat16* lo,
                                            size_t idx, float z) {
    __nv_bfloat16 h = __float2bfloat16(z);
    hi[idx] = h;
    lo[idx] = __float2bfloat16(z - __bfloat162float(h));
}

// ---------------- weight split ----------------
__global__ void k_wsplit(const float* __restrict__ Wg, const float* __restrict__ Ws,
                         const float* __restrict__ Wih, const float* __restrict__ Whh,
                         __nv_bfloat16* __restrict__ hi, __nv_bfloat16* __restrict__ lo) {
    int idx = blockIdx.x * blockDim.x + threadIdx.x;
    int row = idx >> 7, c = idx & 127;
    float w;
    if (row < 256)       w = Wg[(size_t)row * 128 + c];
    else if (row < 512)  w = Ws[(size_t)(row - 256) * 128 + c];
    else if (row < 1280) w = Wih[(size_t)(row - 512) * 128 + c];
    else                 w = Whh[(size_t)(row - 1280) * 128 + c];
    write_split(hi, lo, idx, w);
}

// ---------------- activation split (node_attr) ----------------
__global__ void k_xsplit(const float* __restrict__ X, __nv_bfloat16* __restrict__ hi,
                         __nv_bfloat16* __restrict__ lo, int n4) {
    int i = blockIdx.x * blockDim.x + threadIdx.x;
    if (i >= n4) return;
    float4 x = reinterpret_cast<const float4*>(X)[i];
    __nv_bfloat162 h01 = __floats2bfloat162_rn(x.x, x.y);
    __nv_bfloat162 h23 = __floats2bfloat162_rn(x.z, x.w);
    __nv_bfloat162 l01 = __floats2bfloat162_rn(x.x - __bfloat162float(h01.x),
                                               x.y - __bfloat162float(h01.y));
    __nv_bfloat162 l23 = __floats2bfloat162_rn(x.z - __bfloat162float(h23.x),
                                               x.w - __bfloat162float(h23.y));
    reinterpret_cast<uint2*>(hi)[i] =
        make_uint2(*reinterpret_cast<uint32_t*>(&h01), *reinterpret_cast<uint32_t*>(&h23));
    reinterpret_cast<uint2*>(lo)[i] =
        make_uint2(*reinterpret_cast<uint32_t*>(&l01), *reinterpret_cast<uint32_t*>(&l23));
}

// ---------------- wmma GEMM v4: Y = X @ W^T, 3-term bf16 split,
// 128x128 tile, 1 CTA/SM, A double-buffered cp.async pipeline ----------------
#define LDA 136
#define TILE_BYTES (128 * LDA * 2)           // one 128-row bf16 tile (hi or lo) = 34,816
#define BH_OFF 0
#define BL_OFF TILE_BYTES
#define A_OFF (2 * TILE_BYTES)               // stage s: Ah at A_OFF + s*2*TILE, Al next
#define GEMM_SMEM (A_OFF + 4 * TILE_BYTES)   // 69,632 + 139,264 = 208,896 B

__global__ __launch_bounds__(256) void k_gemm_tc(
    const __nv_bfloat16* __restrict__ Xhi, const __nv_bfloat16* __restrict__ Xlo,
    const __nv_bfloat16* __restrict__ bhi, const __nv_bfloat16* __restrict__ blo,
    float* __restrict__ Y, int M, int Nout) {
    extern __shared__ char smem[];
    __nv_bfloat16* Bh = reinterpret_cast<__nv_bfloat16*>(smem + BH_OFF);
    __nv_bfloat16* Bl = reinterpret_cast<__nv_bfloat16*>(smem + BL_OFF);

    int tid = threadIdx.x, wid = tid >> 5;
    int tn = blockIdx.y;
    int ntiles = (M + 127) >> 7;
    if ((int)blockIdx.x >= ntiles) return;
    uint32_t sb = smem_u32(smem);

    // B tile (once per block)
    for (int i = tid; i < 128 * 16; i += 256) {
        int r = i >> 4, c = i & 15;
        cp16(sb + BH_OFF + r * (LDA * 2) + c * 16, &bhi[(size_t)(tn * 128 + r) * 128 + c * 8]);
        cp16(sb + BL_OFF + r * (LDA * 2) + c * 16, &blo[(size_t)(tn * 128 + r) * 128 + c * 8]);
    }
    CP_COMMIT;

    auto load_a = [&](int tm, int st) {
        int row0 = tm * 128;
        uint32_t base = sb + A_OFF + st * 2 * TILE_BYTES;
        for (int i = tid; i < 128 * 16; i += 256) {
            int r = i >> 4, c = i & 15;
            int gr = row0 + r;
            if (gr >= M) gr = M - 1;
            cp16(base + r * (LDA * 2) + c * 16, &Xhi[(size_t)gr * 128 + c * 8]);
            cp16(base + TILE_BYTES + r * (LDA * 2) + c * 16, &Xlo[(size_t)gr * 128 + c * 8]);
        }
        CP_COMMIT;
    };

    // prologue: stage 0
    load_a(blockIdx.x, 0);

    int wm = wid & 1, wn = wid >> 1;  // wm: 2 x 64 rows, wn: 4 x 32 cols
    int st = 0;
    for (int tm = blockIdx.x; tm < ntiles; tm += gridDim.x, st ^= 1) {
        // issue next A into the other stage (freed by last iteration's trailing sync)
        int tmn = tm + gridDim.x;
        if (tmn >= ntiles) tmn = tm;    // harmless reload
        load_a(tmn, st ^ 1);
        CP_WAIT(1);                     // current stage (and B) complete; next may fly
        __syncthreads();

        __nv_bfloat16* Ah = reinterpret_cast<__nv_bfloat16*>(smem + A_OFF + st * 2 * TILE_BYTES);
        __nv_bfloat16* Al = Ah + 128 * LDA;

        wmma::fragment<wmma::accumulator, 16, 16, 16, float> cf[4][2];
#pragma unroll
        for (int i = 0; i < 4; i++)
#pragma unroll
            for (int j = 0; j < 2; j++) wmma::fill_fragment(cf[i][j], 0.f);

        const __nv_bfloat16* Aterm[3] = {Ah, Ah, Al};
        const __nv_bfloat16* Bterm[3] = {Bh, Bl, Bh};
#pragma unroll
        for (int t = 0; t < 3; t++) {
            const __nv_bfloat16* As = Aterm[t];
            const __nv_bfloat16* Bs = Bterm[t];
#pragma unroll
            for (int k0 = 0; k0 < 128; k0 += 16) {
                wmma::fragment<wmma::matrix_a, 16, 16, 16, __nv_bfloat16, wmma::row_major> a[4];
                wmma::fragment<wmma::matrix_b, 16, 16, 16, __nv_bfloat16, wmma::col_major> b[2];
#pragma unroll
                for (int i = 0; i < 4; i++)
                    wmma::load_matrix_sync(a[i], &As[(wm * 64 + i * 16) * LDA + k0], LDA);
#pragma unroll
                for (int j = 0; j < 2; j++)
                    wmma::load_matrix_sync(b[j], &Bs[(wn * 32 + j * 16) * LDA + k0], LDA);
#pragma unroll
                for (int i = 0; i < 4; i++)
#pragma unroll
                    for (int j = 0; j < 2; j++) wmma::mma_sync(cf[i][j], a[i], b[j], cf[i][j]);
            }
        }
        // direct store (M always multiple of 16)
        int row0 = tm * 128;
#pragma unroll
        for (int i = 0; i < 4; i++) {
            int row = row0 + wm * 64 + i * 16;
            if (row + 16 <= M) {
#pragma unroll
                for (int j = 0; j < 2; j++)
                    wmma::store_matrix_sync(&Y[(size_t)row * Nout + tn * 128 + wn * 32 + j * 16],
                                            cf[i][j], Nout, wmma::mem_row_major);
            }
        }
        __syncthreads();  // stage 'st' free for the cp.async issued next iteration
    }
}

// ---------------- small helpers ----------------
__device__ __forceinline__ float bn_apply(float x, int idx, int ch,
                                          const float* g, const float* b,
                                          const float* m, const float* v) {
    float sc = g[idx * CC + ch] * rsqrtf(v[idx * CC + ch] + 1e-5f);
    return (x - m[idx * CC + ch]) * sc + b[idx * CC + ch];
}
__device__ __forceinline__ float warp_max(float v) {
#pragma unroll
    for (int o = 16; o > 0; o >>= 1) v = fmaxf(v, __shfl_xor_sync(0xffffffffu, v, o));
    return v;
}
__device__ __forceinline__ float warp_sum(float v) {
#pragma unroll
    for (int o = 16; o > 0; o >>= 1) v += __shfl_xor_sync(0xffffffffu, v, o);
    return v;
}

// ---------------- CSR build ----------------
__global__ void k_zero_int(int* p, int n) {
    int i = blockIdx.x * blockDim.x + threadIdx.x;
    if (i < n) p[i] = 0;
}
__global__ void k_hist(const int* __restrict__ idx0, int* __restrict__ cnt) {
    int e = blockIdx.x * blockDim.x + threadIdx.x;
    if (e < EE) atomicAdd(&cnt[idx0[e]], 1);
}
__global__ void k_scan1(const int* __restrict__ in, int* __restrict__ out,
                        int* __restrict__ bsum, int n) {
    __shared__ int sm[1024];
    int i = blockIdx.x * 1024 + threadIdx.x;
    int v = (i < n) ? in[i] : 0;
    sm[threadIdx.x] = v;
    __syncthreads();
    for (int off = 1; off < 1024; off <<= 1) {
        int t = (threadIdx.x >= off) ? sm[threadIdx.x - off] : 0;
        __syncthreads();
        sm[threadIdx.x] += t;
        __syncthreads();
    }
    if (i < n) out[i] = sm[threadIdx.x] - v;
    if (threadIdx.x == 1023) bsum[blockIdx.x] = sm[1023];
}
__global__ void k_scan2(int* __restrict__ bsum, int nb) {
    __shared__ int sm[256];
    int v = (threadIdx.x < nb) ? bsum[threadIdx.x] : 0;
    sm[threadIdx.x] = v;
    __syncthreads();
    for (int off = 1; off < 256; off <<= 1) {
        int t = (threadIdx.x >= off) ? sm[threadIdx.x - off] : 0;
        __syncthreads();
        sm[threadIdx.x] += t;
        __syncthreads();
    }
    if (threadIdx.x < nb) bsum[threadIdx.x] = sm[threadIdx.x] - v;
}
__global__ void k_scan3(int* __restrict__ out, const int* __restrict__ bsum,
                        int n, int total, int* __restrict__ cursor) {
    int i = blockIdx.x * 1024 + threadIdx.x;
    if (i < n) {
        int v = out[i] + bsum[blockIdx.x];
        out[i] = v;
        cursor[i] = v;
    }
    if (i == 0) out[n] = total;
}
__global__ void k_scatter(const int* __restrict__ adj, const float* __restrict__ aval,
                          int* __restrict__ cursor, int* __restrict__ col,
                          float* __restrict__ val) {
    int e = blockIdx.x * blockDim.x + threadIdx.x;
    if (e >= EE) return;
    int r = adj[e];
    int p = atomicAdd(&cursor[r], 1);
    col[p] = adj[EE + e];
    val[p] = aval[e];
}
__global__ void k_segoff(const int* __restrict__ seg, int n, int nseg, int* __restrict__ off) {
    int i = blockIdx.x * blockDim.x + threadIdx.x;
    if (i >= n) return;
    int s = seg[i];
    int p = (i == 0) ? -1 : seg[i - 1];
    for (int t = p + 1; t <= s; ++t) off[t] = i;
    if (i == n - 1)
        for (int t = s + 1; t <= nseg; ++t) off[t] = n;
}

// ---------------- SpMM + bias + BN(+relu)(+BN2), f32/bf16-split out, fused rowdot ----------------
__global__ void k_spmm(const float* __restrict__ Xin, float* __restrict__ Yf,
                       __nv_bfloat16* __restrict__ Yhi, __nv_bfloat16* __restrict__ Ylo,
                       const int* __restrict__ rowoff, const int* __restrict__ col,
                       const float* __restrict__ val, const float* __restrict__ bias,
                       const float* __restrict__ vsrc, float* __restrict__ svout,
                       const float* __restrict__ bg, const float* __restrict__ bb,
                       const float* __restrict__ bm, const float* __restrict__ bv,
                       int bnA, int bnB, int M) {
    int gw = (blockIdx.x * blockDim.x + threadIdx.x) >> 5;
    int lane = threadIdx.x & 31;
    if (gw >= M) return;
    int s = rowoff[gw], e = rowoff[gw + 1];
    float acc[4] = {0.f, 0.f, 0.f, 0.f};
    int i = s;
    for (; i + 1 < e; i += 2) {
        int c0 = col[i], c1 = col[i + 1];
        float v0 = val[i], v1 = val[i + 1];
        const float* x0 = Xin + (size_t)c0 * CC;
        const float* x1 = Xin + (size_t)c1 * CC;
#pragma unroll
        for (int j = 0; j < 4; j++)
            acc[j] += v0 * x0[lane + 32 * j] + v1 * x1[lane + 32 * j];
    }
    if (i < e) {
        int c0 = col[i];
        float v0 = val[i];
        const float* x0 = Xin + (size_t)c0 * CC;
#pragma unroll
        for (int j = 0; j < 4; j++) acc[j] += v0 * x0[lane + 32 * j];
    }
    float sdot = 0.f;
#pragma unroll
    for (int j = 0; j < 4; j++) {
        int ch = lane + 32 * j;
        float z = acc[j] + bias[ch];
        z = bn_apply(z, bnA, ch, bg, bb, bm, bv);
        z = fmaxf(z, 0.f);
        if (bnB >= 0) z = bn_apply(z, bnB, ch, bg, bb, bm, bv);
        size_t idx = (size_t)gw * CC + ch;
        if (Yf) Yf[idx] = z;
        if (Yhi) write_split(Yhi, Ylo, idx, z);
        if (vsrc) sdot += z * vsrc[ch];
    }
    if (vsrc) {
        sdot = warp_sum(sdot);
        if (lane == 0) svout[gw] = sdot;
    }
}

// ---------------- segment sum pool + relu + BN; f32 + bf16-split out ----------------
__global__ void k_segpool(const float* __restrict__ X, float* __restrict__ Yf,
                          __nv_bfloat16* __restrict__ Yhi, __nv_bfloat16* __restrict__ Ylo,
                          const int* __restrict__ off, int nseg,
                          const float* bg, const float* bb, const float* bm,
                          const float* bv, int bi) {
    int gw = (blockIdx.x * blockDim.x + threadIdx.x) >> 5;
    int lane = threadIdx.x & 31;
    if (gw >= nseg) return;
    int s = off[gw], e = off[gw + 1];
    float acc[4] = {0.f, 0.f, 0.f, 0.f};
    for (int i = s; i < e; i++) {
        const float* xr = X + (size_t)i * CC;
#pragma unroll
        for (int j = 0; j < 4; j++) acc[j] += xr[lane + 32 * j];
    }
#pragma unroll
    for (int j = 0; j < 4; j++) {
        int ch = lane + 32 * j;
        float z = bn_apply(fmaxf(acc[j], 0.f), bi, ch, bg, bb, bm, bv);
        size_t idx = (size_t)gw * CC + ch;
        Yf[idx] = z;
        write_split(Yhi, Ylo, idx, z);
    }
}

// vd[c] = sum_o ad[o] * Wd[o,c]
__global__ void k_vd(const float* __restrict__ Wd, const float* __restrict__ ad,
                     float* __restrict__ vd) {
    int c = threadIdx.x;
    float s = 0.f;
    for (int o = 0; o < CC; o++) s += ad[o] * Wd[o * CC + c];
    vd[c] = s;
}
__global__ void k_rowdot(const float* __restrict__ X, const float* __restrict__ v,
                         float* __restrict__ out, int M) {
    int gw = (blockIdx.x * blockDim.x + threadIdx.x) >> 5;
    int lane = threadIdx.x & 31;
    if (gw >= M) return;
    const float* xr = X + (size_t)gw * CC;
    float s = 0.f;
#pragma unroll
    for (int j = 0; j < 4; j++) s += xr[lane + 32 * j] * v[lane + 32 * j];
    s = warp_sum(s);
    if (lane == 0) out[gw] = s;
}

// ---------------- GAT softmax + aggregate + bias + ELU -> bf16-split out ----------------
__global__ void k_gat(const float* __restrict__ hs, const float* __restrict__ ssrc,
                      const float* __restrict__ sdst, const int* __restrict__ off,
                      const float* __restrict__ bias, __nv_bfloat16* __restrict__ outhi,
                      __nv_bfloat16* __restrict__ outlo, int nseg) {
    int gw = (blockIdx.x * blockDim.x + threadIdx.x) >> 5;
    int lane = threadIdx.x & 31;
    if (gw >= nseg) return;
    int s = off[gw], e = off[gw + 1];
    float sd = sdst[gw];
    float acc[4] = {0.f, 0.f, 0.f, 0.f};
    if (e > s) {
        float mx = -3.402823e38f;
        for (int i = s + lane; i < e; i += 32) {
            float a = ssrc[i] + sd;
            a = a > 0.f ? a : 0.01f * a;
            mx = fmaxf(mx, a);
        }
        mx = warp_max(mx);
        float den = 0.f;
        for (int i = s + lane; i < e; i += 32) {
            float a = ssrc[i] + sd;
            a = a > 0.f ? a : 0.01f * a;
            den += __expf(a - mx);
        }
        den = warp_sum(den);
        float inv = 1.f / den;
        for (int i = s; i < e; i++) {
            float a = ssrc[i] + sd;
            a = a > 0.f ? a : 0.01f * a;
            float w = __expf(a - mx) * inv;
            const float* hr = hs + (size_t)i * CC;
#pragma unroll
            for (int j = 0; j < 4; j++) acc[j] += w * hr[lane + 32 * j];
        }
    }
#pragma unroll
    for (int j = 0; j < 4; j++) {
        int ch = lane + 32 * j;
        float v = acc[j] + bias[ch];
        v = v > 0.f ? v : (__expf(v) - 1.f);  // ELU
        write_split(outhi, outlo, (size_t)gw * CC + ch, v);
    }
}

// ---------------- GRU gates (+ folded biases) + relu + BN(+BN2) ----------------
__global__ void k_gru(const float* __restrict__ gi, const float* __restrict__ gh,
                      const float* __restrict__ h, const float* __restrict__ bih,
                      const float* __restrict__ bhh, float* __restrict__ outf,
                      __nv_bfloat16* __restrict__ outhi, __nv_bfloat16* __restrict__ outlo,
                      int M, const float* bg, const float* bb, const float* bm,
                      const float* bv, int bnA, int bnB) {
    int idx = blockIdx.x * blockDim.x + threadIdx.x;
    if (idx >= M * CC) return;
    int t = idx >> 7, c = idx & 127;
    const float* gir = gi + (size_t)t * 3 * CC;
    const float* ghr = gh + (size_t)t * 3 * CC;
    float r = 1.f / (1.f + __expf(-(gir[c] + bih[c] + ghr[c] + bhh[c])));
    float z = 1.f / (1.f + __expf(-(gir[CC + c] + bih[CC + c] + ghr[CC + c] + bhh[CC + c])));
    float n = tanhf(gir[2 * CC + c] + bih[2 * CC + c] +
                    r * (ghr[2 * CC + c] + bhh[2 * CC + c]));
    float hv = (1.f - z) * n + z * h[idx];
    float y = fmaxf(hv, 0.f);
    y = bn_apply(y, bnA, c, bg, bb, bm, bv);
    if (bnB >= 0) y = bn_apply(y, bnB, c, bg, bb, bm, bv);
    outf[idx] = y;
    if (outhi) write_split(outhi, outlo, idx, y);
}

// ---------------- predictor ----------------
__global__ void k_pred(const float* __restrict__ mol, const float* __restrict__ W1,
                       const float* __restrict__ b1, const float* __restrict__ W2,
                       const float* __restrict__ b2, float* __restrict__ out) {
    __shared__ float xr[CC];
    __shared__ float hr[64];
    int m = blockIdx.x, t = threadIdx.x;
    xr[t] = mol[(size_t)m * CC + t];
    xr[t + 64] = mol[(size_t)m * CC + t + 64];
    __syncthreads();
    float s = b1[t];
    for (int c = 0; c < CC; c++) s += W1[t * CC + c] * xr[c];
    s = fmaxf(s, 0.f);
    hr[t] = s * W2[t];
    __syncthreads();
    for (int off = 32; off > 0; off >>= 1) {
        if (t < off) hr[t] += hr[t + off];
        __syncthreads();
    }
    if (t == 0) out[m] = hr[0] + b2[0];
}

// ---------------- host ----------------
extern "C" void kernel_launch(void* const* d_in, const int* in_sizes, int n_in,
                              void* d_out, int out_size) {
    if (n_in < 24) return;
    const float *node_attr, *adj_value, *W_gcn, *b_gcn, *bg, *bb, *bm, *bv;
    const float *Wsrc, *Wdst, *asrc, *adst, *gbias, *Wih, *Whh, *bih, *bhh;
    const float *pW1, *pb1, *pW2, *pb2;
    const int *adj_index, *ttb, *tgb;
    if (in_sizes[1] == EE) {
        node_attr = (const float*)d_in[0];  adj_value = (const float*)d_in[1];
        W_gcn = (const float*)d_in[2];      b_gcn = (const float*)d_in[3];
        bg = (const float*)d_in[4];         bb = (const float*)d_in[5];
        bm = (const float*)d_in[6];         bv = (const float*)d_in[7];
        Wsrc = (const float*)d_in[8];       Wdst = (const float*)d_in[9];
        asrc = (const float*)d_in[10];      adst = (const float*)d_in[11];
        gbias = (const float*)d_in[12];     Wih = (const float*)d_in[13];
        Whh = (const float*)d_in[14];       bih = (const float*)d_in[15];
        bhh = (const float*)d_in[16];       pW1 = (const float*)d_in[17];
        pb1 = (const float*)d_in[18];       pW2 = (const float*)d_in[19];
        pb2 = (const float*)d_in[20];       adj_index = (const int*)d_in[21];
        ttb = (const int*)d_in[22];         tgb = (const int*)d_in[23];
    } else {
        node_attr = (const float*)d_in[0];  adj_index = (const int*)d_in[1];
        adj_value = (const float*)d_in[2];  ttb = (const int*)d_in[3];
        tgb = (const int*)d_in[4];          W_gcn = (const float*)d_in[5];
        b_gcn = (const float*)d_in[6];      bg = (const float*)d_in[7];
        bb = (const float*)d_in[8];         bm = (const float*)d_in[9];
        bv = (const float*)d_in[10];        Wsrc = (const float*)d_in[11];
        Wdst = (const float*)d_in[12];      asrc = (const float*)d_in[13];
        adst = (const float*)d_in[14];      gbias = (const float*)d_in[15];
        Wih = (const float*)d_in[16];       Whh = (const float*)d_in[17];
        bih = (const float*)d_in[18];       bhh = (const float*)d_in[19];
        pW1 = (const float*)d_in[20];       pb1 = (const float*)d_in[21];
        pW2 = (const float*)d_in[22];       pb2 = (const float*)d_in[23];
    }

    void* p;
    cudaGetSymbolAddress(&p, g_t1);        float* t1 = (float*)p;
    cudaGetSymbolAddress(&p, g_t2);        float* t2 = (float*)p;
    cudaGetSymbolAddress(&p, g_hs);        float* hs = (float*)p;
    cudaGetSymbolAddress(&p, g_hs2);       float* hs2 = (float*)p;
    cudaGetSymbolAddress(&p, g_cnt);       int* cnt = (int*)p;
    cudaGetSymbolAddress(&p, g_rowoff);    int* rowoff = (int*)p;
    cudaGetSymbolAddress(&p, g_cursor);    int* cursor = (int*)p;
    cudaGetSymbolAddress(&p, g_bsum);      int* bsum = (int*)p;
    cudaGetSymbolAddress(&p, g_col);       int* col = (int*)p;
    cudaGetSymbolAddress(&p, g_val);       float* val = (float*)p;
    cudaGetSymbolAddress(&p, g_ttoff);     int* ttoff = (int*)p;
    cudaGetSymbolAddress(&p, g_moloff);    int* moloff = (int*)p;
    cudaGetSymbolAddress(&p, g_meanbn_tt); float* meanbn_tt = (float*)p;
    cudaGetSymbolAddress(&p, g_gi_tt);     float* gi_tt = (float*)p;
    cudaGetSymbolAddress(&p, g_gh_tt);     float* gh_tt = (float*)p;
    cudaGetSymbolAddress(&p, g_ttbn);      float* ttbn = (float*)p;
    cudaGetSymbolAddress(&p, g_meanbn_mol);float* meanbn_mol = (float*)p;
    cudaGetSymbolAddress(&p, g_gi_mol);    float* gi_mol = (float*)p;
    cudaGetSymbolAddress(&p, g_gh_mol);    float* gh_mol = (float*)p;
    cudaGetSymbolAddress(&p, g_molout);    float* molout = (float*)p;
    cudaGetSymbolAddress(&p, g_ssrc);      float* ssrc = (float*)p;
    cudaGetSymbolAddress(&p, g_sdst);      float* sdst = (float*)p;
    cudaGetSymbolAddress(&p, g_vsrc);      float* vsrc = (float*)p;
    cudaGetSymbolAddress(&p, g_vdst);      float* vdst = (float*)p;
    cudaGetSymbolAddress(&p, g_whi);       __nv_bfloat16* whi = (__nv_bfloat16*)p;
    cudaGetSymbolAddress(&p, g_wlo);       __nv_bfloat16* wlo = (__nv_bfloat16*)p;
    cudaGetSymbolAddress(&p, g_xhi);       __nv_bfloat16* xhi = (__nv_bfloat16*)p;
    cudaGetSymbolAddress(&p, g_xlo);       __nv_bfloat16* xlo = (__nv_bfloat16*)p;
    cudaGetSymbolAddress(&p, g_phi);       __nv_bfloat16* phi = (__nv_bfloat16*)p;
    cudaGetSymbolAddress(&p, g_plo);       __nv_bfloat16* plo = (__nv_bfloat16*)p;
    cudaGetSymbolAddress(&p, g_ghi);       __nv_bfloat16* ghi = (__nv_bfloat16*)p;
    cudaGetSymbolAddress(&p, g_glo);       __nv_bfloat16* glo = (__nv_bfloat16*)p;
    float* outp = (float*)d_out;

    cudaFuncSetAttribute(k_gemm_tc, cudaFuncAttributeMaxDynamicSharedMemorySize, GEMM_SMEM);

    auto gemm = [&](const __nv_bfloat16* xh, const __nv_bfloat16* xl, int wrow,
                    float* Y, int M, int Nout) {
        int ntiles = (M + 127) / 128;
        int gy = Nout / 128;
        int gxmax = 148 / gy; if (gxmax < 1) gxmax = 1;
        int gx = ntiles < gxmax ? ntiles : gxmax;
        dim3 grid(gx, gy);
        k_gemm_tc<<<grid, 256, GEMM_SMEM>>>(xh, xl, whi + (size_t)wrow * 128,
                                            wlo + (size_t)wrow * 128, Y, M, Nout);
    };

    // index 3 = first big GEMM (ncu capture slot)
    k_wsplit<<<1024, 256>>>(W_gcn, Wsrc, Wih, Whh, whi, wlo);                // 0
    k_xsplit<<<(NN * 32 + 255) / 256, 256>>>(node_attr, xhi, xlo, NN * 32);  // 1
    k_zero_int<<<(NN + 255) / 256, 256>>>(cnt, NN);                          // 2
    gemm(xhi, xlo, WR_G0, t1, NN, 128);                                      // 3
    k_hist<<<(EE + 255) / 256, 256>>>(adj_index, cnt);
    k_scan1<<<196, 1024>>>(cnt, rowoff, bsum, NN);
    k_scan2<<<1, 256>>>(bsum, 196);
    k_scan3<<<196, 1024>>>(rowoff, bsum, NN, EE, cursor);
    k_scatter<<<(EE + 255) / 256, 256>>>(adj_index, adj_value, cursor, col, val);
    k_segoff<<<(NN + 255) / 256, 256>>>(ttb, NN, NTTS, ttoff);
    k_segoff<<<(NTTS + 255) / 256, 256>>>(tgb, NTTS, NMOLS, moloff);
    k_vd<<<1, 128>>>(Wsrc, asrc, vsrc);
    k_vd<<<1, 128>>>(Wdst, adst, vdst);

    // GCN layer 0 -> xhi/xlo only
    k_spmm<<<NN / 8, 256>>>(t1, nullptr, xhi, xlo, rowoff, col, val, b_gcn,
                            nullptr, nullptr, bg, bb, bm, bv, 0, -1, NN);
    // GCN layer 1 (+ fused bn2) -> t2 f32 + split + fused ssrc rowdot
    gemm(xhi, xlo, WR_G1, t1, NN, 128);
    k_spmm<<<NN / 8, 256>>>(t1, t2, xhi, xlo, rowoff, col, val, b_gcn + CC,
                            vsrc, ssrc, bg, bb, bm, bv, 1, 2, NN);

    // tt stage
    k_segpool<<<(NTTS * 32 + 255) / 256, 256>>>(t2, meanbn_tt, phi, plo, ttoff, NTTS,
                                                bg, bb, bm, bv, 3);
    gemm(xhi, xlo, WR_S0, hs, NN, 128);
    k_rowdot<<<(NTTS * 32 + 255) / 256, 256>>>(meanbn_tt, vdst, sdst, NTTS);
    k_gat<<<(NTTS * 32 + 255) / 256, 256>>>(hs, ssrc, sdst, ttoff, gbias, ghi, glo, NTTS);
    gemm(ghi, glo, WR_IH0, gi_tt, NTTS, 384);
    gemm(phi, plo, WR_HH0, gh_tt, NTTS, 384);
    k_gru<<<(NTTS * CC + 255) / 256, 256>>>(gi_tt, gh_tt, meanbn_tt, bih, bhh,
                                            ttbn, ghi, glo, NTTS, bg, bb, bm, bv, 4, 5);

    // mol stage
    k_segpool<<<(NMOLS * 32 + 255) / 256, 256>>>(ttbn, meanbn_mol, phi, plo, moloff, NMOLS,
                                                 bg, bb, bm, bv, 6);
    gemm(ghi, glo, WR_S1, hs2, NTTS, 128);
    k_vd<<<1, 128>>>(Wsrc + CC * CC, asrc + CC, vsrc);
    k_vd<<<1, 128>>>(Wdst + CC * CC, adst + CC, vdst);
    k_rowdot<<<(NTTS * 32 + 255) / 256, 256>>>(ttbn, vsrc, ssrc, NTTS);
    k_rowdot<<<(NMOLS * 32 + 255) / 256, 256>>>(meanbn_mol, vdst, sdst, NMOLS);
    k_gat<<<(NMOLS * 32 + 255) / 256, 256>>>(hs2, ssrc, sdst, moloff, gbias + CC,
                                             ghi, glo, NMOLS);
    gemm(ghi, glo, WR_IH1, gi_mol, NMOLS, 384);
    gemm(phi, plo, WR_HH1, gh_mol, NMOLS, 384);
    k_gru<<<(NMOLS * CC + 255) / 256, 256>>>(gi_mol, gh_mol, meanbn_mol, bih + 3 * CC,
                                             bhh + 3 * CC, molout, nullptr, nullptr,
                                             NMOLS, bg, bb, bm, bv, 7, -1);

    // predictor
    k_pred<<<NMOLS, 64>>>(molout, pW1, pb1, pW2, pb2, outp);
}